// round 2
// baseline (speedup 1.0000x reference)
#include <cuda_runtime.h>
#include <math.h>

// Problem constants
#define BSZ 8
#define HW 32
#define DMODEL 128
#define NHEADS 8
#define SCALE 0.08838834764831845f   // 1/sqrt(128)

// Scratch (allocation-free rule: __device__ globals)
__device__ float g_x  [BSZ*HW*HW*DMODEL];            // 4 MB   LayerNorm output
__device__ float g_q  [BSZ*HW*HW*NHEADS*DMODEL];     // 32 MB  q[b][i][j][h][d]
__device__ float g_k  [BSZ*HW*HW*NHEADS*DMODEL];     // 32 MB  k[b][i][j][h][d]
__device__ float g_ctx[BSZ*HW*HW*NHEADS*DMODEL];     // 32 MB  ctx[b][j][i][h*128+d]

// ---------------------------------------------------------------- LayerNorm
__global__ void ln_kernel(const float* __restrict__ hs,
                          const float* __restrict__ gam,
                          const float* __restrict__ bet) {
    int row = blockIdx.x;          // 8192 rows
    int c   = threadIdx.x;         // 128
    float v = hs[row*128 + c];
    float s = v, s2 = v*v;
    #pragma unroll
    for (int o = 16; o >= 1; o >>= 1) {
        s  += __shfl_xor_sync(0xffffffffu, s,  o);
        s2 += __shfl_xor_sync(0xffffffffu, s2, o);
    }
    __shared__ float ws[4], ws2[4];
    int w = c >> 5;
    if ((c & 31) == 0) { ws[w] = s; ws2[w] = s2; }
    __syncthreads();
    s  = ws[0] + ws[1] + ws[2] + ws[3];
    s2 = ws2[0] + ws2[1] + ws2[2] + ws2[3];
    float mu  = s  * (1.0f/128.0f);
    float var = s2 * (1.0f/128.0f) - mu*mu;
    float r   = rsqrtf(var + 1e-5f);
    g_x[row*128 + c] = (v - mu) * r * gam[c] + bet[c];
}

// ------------------------------------------------- fused Q,K projection GEMM
// out[r, o] = sum_c x[r,c] * W[o,c],  W = [Wq; Wk] stacked (2048 x 128)
__global__ void __launch_bounds__(256) qk_kernel(const float* __restrict__ Wq,
                                                 const float* __restrict__ Wk) {
    __shared__ float As[64*65];
    __shared__ float Bs[64*65];
    int bx = blockIdx.x;           // 128 row tiles of 64
    int by = blockIdx.y;           // 32 col tiles of 64
    int t  = threadIdx.x;
    int ty = t >> 4, tx = t & 15;
    float acc[4][4] = {};
    for (int kt = 0; kt < 2; kt++) {
        __syncthreads();
        for (int e = t; e < 64*64; e += 256) {
            int r = e >> 6, c = e & 63;
            As[r*65 + c] = g_x[(bx*64 + r)*128 + kt*64 + c];
            int o = by*64 + r;
            const float* W = (o < 1024) ? (Wq + o*128) : (Wk + (o-1024)*128);
            Bs[r*65 + c] = W[kt*64 + c];
        }
        __syncthreads();
        #pragma unroll 8
        for (int c = 0; c < 64; c++) {
            float a[4], b[4];
            #pragma unroll
            for (int u = 0; u < 4; u++) a[u] = As[(ty + 16*u)*65 + c];
            #pragma unroll
            for (int v = 0; v < 4; v++) b[v] = Bs[(tx + 16*v)*65 + c];
            #pragma unroll
            for (int u = 0; u < 4; u++)
                #pragma unroll
                for (int v = 0; v < 4; v++) acc[u][v] += a[u]*b[v];
        }
    }
    #pragma unroll
    for (int u = 0; u < 4; u++)
        #pragma unroll
        for (int v = 0; v < 4; v++) {
            int row = bx*64 + ty + 16*u;
            int col = by*64 + tx + 16*v;
            if (col < 1024) g_q[(size_t)row*1024 + col]          = acc[u][v];
            else            g_k[(size_t)row*1024 + (col - 1024)] = acc[u][v];
        }
}

// --------------------------------------------------------- fused attention
// Block = (b, h, i=qt); queries q=j in [0,32). Scores stored S[q][l*32+k]
// (already in probs output order). Keys tiled by l.
#define SS_OFF 0          // 32*1025 = 32800
#define QS_OFF 32800      // 32*129  = 4128
#define KS_OFF 36928      // 32*129  = 4128
#define XS_OFF 41056      // 32*128  = 4096
#define RR_OFF 45152      // 1024
#define RC_OFF 46176      // 1024
#define RZ_OFF 47200      // 32
#define SMEM_FLOATS 47232 // *4 = 188928 bytes

__global__ void __launch_bounds__(256) attn_kernel(
    const float* __restrict__ row_emb, const float* __restrict__ col_emb,
    float* __restrict__ probs, int write_probs)
{
    extern __shared__ float sm[];
    float* Ss = sm + SS_OFF;
    float* Qs = sm + QS_OFF;
    float* Ks = sm + KS_OFF;
    float* Xs = sm + XS_OFF;
    float* rr = sm + RR_OFF;
    float* rc = sm + RC_OFF;
    float* rz = sm + RZ_OFF;

    const int qt = blockIdx.x;   // i
    const int h  = blockIdx.y;
    const int b  = blockIdx.z;
    const int t  = threadIdx.x;

    // A: load Q tile (32 queries x 128)
    const float* qbase = g_q + (size_t)b*1048576 + (size_t)qt*32768 + h*128;
    for (int e = t; e < 4096; e += 256) {
        int jq = e >> 7, d = e & 127;
        Qs[jq*129 + d] = qbase[(size_t)jq*1024 + d];
    }
    __syncthreads();

    // B: relative-position terms  rr[q][k], rc[q][l]
    for (int e = t; e < 2048; e += 256) {
        if (e < 1024) {
            int jq = e >> 5, k = e & 31;
            const float* er = row_emb + (k - qt + 31)*64;
            const float* qv = Qs + jq*129;
            float s = 0.f;
            #pragma unroll 16
            for (int d = 0; d < 64; d++) s += qv[d]*er[d];
            rr[e] = s;
        } else {
            int e2 = e - 1024;
            int jq = e2 >> 5, l = e2 & 31;
            const float* ec = col_emb + (l - jq + 31)*64;
            const float* qv = Qs + jq*129 + 64;
            float s = 0.f;
            #pragma unroll 16
            for (int d = 0; d < 64; d++) s += qv[d]*ec[d];
            rc[e2] = s;
        }
    }
    __syncthreads();

    // C: init scores with rel terms (layout S[q][l*32+k])
    for (int e = t; e < 32768; e += 256) {
        int q = e >> 10, rem = e & 1023;
        int l = rem >> 5, k = rem & 31;
        Ss[q*1025 + rem] = rr[q*32 + k] + rc[q*32 + l];
    }

    // D: content scores q . k, key tiles of fixed l
    const int ty = t >> 4, tx = t & 15;
    const float* kbase = g_k + (size_t)b*1048576 + h*128;
    for (int lt = 0; lt < 32; lt++) {
        __syncthreads();
        for (int e = t; e < 4096; e += 256) {
            int kk = e >> 7, d = e & 127;
            Ks[kk*129 + d] = kbase[(size_t)kk*32768 + (size_t)lt*1024 + d];
        }
        __syncthreads();
        float a00=0.f, a01=0.f, a10=0.f, a11=0.f;
        const float* Q0 = Qs + (2*ty)*129;
        const float* Q1 = Q0 + 129;
        const float* K0 = Ks + (2*tx)*129;
        const float* K1 = K0 + 129;
        #pragma unroll 16
        for (int d = 0; d < 128; d++) {
            float q0 = Q0[d], q1 = Q1[d], k0 = K0[d], k1 = K1[d];
            a00 += q0*k0; a01 += q0*k1; a10 += q1*k0; a11 += q1*k1;
        }
        int cb = lt*32;
        Ss[(2*ty  )*1025 + cb + 2*tx    ] += a00;
        Ss[(2*ty  )*1025 + cb + 2*tx + 1] += a01;
        Ss[(2*ty+1)*1025 + cb + 2*tx    ] += a10;
        Ss[(2*ty+1)*1025 + cb + 2*tx + 1] += a11;
    }
    __syncthreads();

    // E: softmax — keep unnormalized exp in smem, rz[q] = 1/Z
    {
        int q = t >> 3, g = t & 7;        // 8 threads per query, same warp
        float* row = Ss + q*1025;
        float m = -1e30f;
        #pragma unroll 8
        for (int mm = 0; mm < 128; mm++) m = fmaxf(m, row[g + 8*mm]);
        m = fmaxf(m, __shfl_xor_sync(0xffffffffu, m, 1));
        m = fmaxf(m, __shfl_xor_sync(0xffffffffu, m, 2));
        m = fmaxf(m, __shfl_xor_sync(0xffffffffu, m, 4));
        float z = 0.f;
        #pragma unroll 8
        for (int mm = 0; mm < 128; mm++) {
            int idx = g + 8*mm;
            float p = __expf(SCALE*(row[idx] - m));
            row[idx] = p;
            z += p;
        }
        z += __shfl_xor_sync(0xffffffffu, z, 1);
        z += __shfl_xor_sync(0xffffffffu, z, 2);
        z += __shfl_xor_sync(0xffffffffu, z, 4);
        if (g == 0) rz[q] = 1.0f / z;
    }
    __syncthreads();

    // F: write probs (layout [b][j=q][i=qt][h][l][k] — matches smem order)
    if (write_probs) {
        size_t pb0 = ((size_t)(b*1024 + qt) * 8 + h) * 1024;
        for (int e = t; e < 32768; e += 256) {
            int q = e >> 10, off = e & 1023;
            probs[pb0 + (size_t)q*262144 + off] = Ss[q*1025 + off] * rz[q];
        }
    }

    // G: context = P @ X  (value position transposed: x[b, l, k, :])
    {
        int q = t & 31, dc = t >> 5;      // thread: 1 query x 16 d-elements
        float acc[16];
        #pragma unroll
        for (int u = 0; u < 16; u++) acc[u] = 0.f;
        const float* xb = g_x + (size_t)b*131072;
        for (int lt = 0; lt < 32; lt++) {
            __syncthreads();
            for (int e = t; e < 4096; e += 256) Xs[e] = xb[lt*4096 + e]; // x[b,lt,0:32,:]
            __syncthreads();
            const float* Prow = Ss + q*1025 + lt*32;
            #pragma unroll 4
            for (int kk = 0; kk < 32; kk++) {
                float p = Prow[kk];
                const float4* xv = (const float4*)(Xs + kk*128 + dc*16);
                float4 x0 = xv[0], x1 = xv[1], x2 = xv[2], x3 = xv[3];
                acc[ 0] += p*x0.x; acc[ 1] += p*x0.y; acc[ 2] += p*x0.z; acc[ 3] += p*x0.w;
                acc[ 4] += p*x1.x; acc[ 5] += p*x1.y; acc[ 6] += p*x1.z; acc[ 7] += p*x1.w;
                acc[ 8] += p*x2.x; acc[ 9] += p*x2.y; acc[10] += p*x2.z; acc[11] += p*x2.w;
                acc[12] += p*x3.x; acc[13] += p*x3.y; acc[14] += p*x3.z; acc[15] += p*x3.w;
            }
        }
        float s = rz[q];
        float* ob = g_ctx + ((size_t)(b*1024 + q*32 + qt))*1024 + h*128 + dc*16;
        #pragma unroll
        for (int u = 0; u < 16; u++) ob[u] = acc[u]*s;
    }
}

// ------------------------------------------ output projection + bias + residual
__global__ void __launch_bounds__(256) out_kernel(const float* __restrict__ Wv,
                                                  const float* __restrict__ bv,
                                                  float* __restrict__ out) {
    __shared__ float As[64*33];
    __shared__ float Bs[128*33];
    int bx = blockIdx.x;              // 128 row tiles of 64
    int t = threadIdx.x, ty = t >> 4, tx = t & 15;
    float acc[4][8] = {};
    for (int ct = 0; ct < 32; ct++) {
        __syncthreads();
        for (int e = t; e < 2048; e += 256) {
            int r = e >> 5, c = e & 31;
            As[r*33 + c] = g_ctx[(size_t)(bx*64 + r)*1024 + ct*32 + c];
        }
        for (int e = t; e < 4096; e += 256) {
            int o = e >> 5, c = e & 31;
            Bs[o*33 + c] = Wv[(size_t)o*1024 + ct*32 + c];
        }
        __syncthreads();
        #pragma unroll 8
        for (int c = 0; c < 32; c++) {
            float a[4], bb[8];
            #pragma unroll
            for (int u = 0; u < 4; u++) a[u] = As[(ty + 16*u)*33 + c];
            #pragma unroll
            for (int v = 0; v < 8; v++) bb[v] = Bs[(tx + 16*v)*33 + c];
            #pragma unroll
            for (int u = 0; u < 4; u++)
                #pragma unroll
                for (int v = 0; v < 8; v++) acc[u][v] += a[u]*bb[v];
        }
    }
    #pragma unroll
    for (int u = 0; u < 4; u++)
        #pragma unroll
        for (int v = 0; v < 8; v++) {
            int r = bx*64 + ty + 16*u;
            int o = tx + 16*v;
            out[(size_t)r*128 + o] = acc[u][v] + bv[o] + g_x[(size_t)r*128 + o];
        }
}

// ---------------------------------------------------------------- launcher
extern "C" void kernel_launch(void* const* d_in, const int* in_sizes, int n_in,
                              void* d_out, int out_size) {
    const float* hs      = (const float*)d_in[0];
    const float* row_emb = (const float*)d_in[1];
    const float* col_emb = (const float*)d_in[2];
    const float* Wq      = (const float*)d_in[3];
    const float* Wk      = (const float*)d_in[4];
    const float* Wv      = (const float*)d_in[5];
    const float* bv      = (const float*)d_in[6];
    const float* ln_g    = (const float*)d_in[7];
    const float* ln_b    = (const float*)d_in[8];
    float* out = (float*)d_out;

    // output tensor = 1,048,576 floats; probs = 67,108,864 floats
    int write_probs = (out_size >= 1048576 + 67108864) ? 1 : 0;
    float* probs = write_probs ? (out + 1048576) : out;

    cudaFuncSetAttribute(attn_kernel, cudaFuncAttributeMaxDynamicSharedMemorySize,
                         SMEM_FLOATS * 4);

    ln_kernel<<<8192, 128>>>(hs, ln_g, ln_b);

    dim3 gqk(128, 32);
    qk_kernel<<<gqk, 256>>>(Wq, Wk);

    dim3 gat(32, NHEADS, BSZ);
    attn_kernel<<<gat, 256, SMEM_FLOATS * 4>>>(row_emb, col_emb, probs, write_probs);

    out_kernel<<<128, 256>>>(Wv, bv, out);
}

// round 4
// speedup vs baseline: 1.4130x; 1.4130x over previous
#include <cuda_runtime.h>
#include <math.h>

// Problem constants
#define BSZ 8
#define HW 32
#define DMODEL 128
#define NHEADS 8
#define SCALE 0.08838834764831845f   // 1/sqrt(128)

// Scratch (allocation-free rule: __device__ globals)
__device__ float g_x  [BSZ*HW*HW*DMODEL];            // 4 MB   LayerNorm output
__device__ float g_q  [BSZ*HW*HW*NHEADS*DMODEL];     // 32 MB  q[b][i][j][h][d]
__device__ float g_k  [BSZ*HW*HW*NHEADS*DMODEL];     // 32 MB  k[b][i][j][h][d]
__device__ float g_ctx[BSZ*HW*HW*NHEADS*DMODEL];     // 32 MB  ctx[b][j][i][h*128+d]

// ---------------------------------------------------------------- LayerNorm
__global__ void ln_kernel(const float* __restrict__ hs,
                          const float* __restrict__ gam,
                          const float* __restrict__ bet) {
    int row = blockIdx.x;          // 8192 rows
    int c   = threadIdx.x;         // 128
    float v = hs[row*128 + c];
    float s = v, s2 = v*v;
    #pragma unroll
    for (int o = 16; o >= 1; o >>= 1) {
        s  += __shfl_xor_sync(0xffffffffu, s,  o);
        s2 += __shfl_xor_sync(0xffffffffu, s2, o);
    }
    __shared__ float ws[4], ws2[4];
    int w = c >> 5;
    if ((c & 31) == 0) { ws[w] = s; ws2[w] = s2; }
    __syncthreads();
    s  = ws[0] + ws[1] + ws[2] + ws[3];
    s2 = ws2[0] + ws2[1] + ws2[2] + ws2[3];
    float mu  = s  * (1.0f/128.0f);
    float var = s2 * (1.0f/128.0f) - mu*mu;
    float r   = rsqrtf(var + 1e-5f);
    g_x[row*128 + c] = (v - mu) * r * gam[c] + bet[c];
}

// ------------------------------------------------- fused Q,K projection GEMM
__global__ void __launch_bounds__(256) qk_kernel(const float* __restrict__ Wq,
                                                 const float* __restrict__ Wk) {
    __shared__ float As[64*65];
    __shared__ float Bs[64*65];
    int bx = blockIdx.x;           // 128 row tiles of 64
    int by = blockIdx.y;           // 32 col tiles of 64
    int t  = threadIdx.x;
    int ty = t >> 4, tx = t & 15;
    float acc[4][4] = {};
    for (int kt = 0; kt < 2; kt++) {
        __syncthreads();
        for (int e = t; e < 64*64; e += 256) {
            int r = e >> 6, c = e & 63;
            As[r*65 + c] = g_x[(bx*64 + r)*128 + kt*64 + c];
            int o = by*64 + r;
            const float* W = (o < 1024) ? (Wq + o*128) : (Wk + (o-1024)*128);
            Bs[r*65 + c] = W[kt*64 + c];
        }
        __syncthreads();
        #pragma unroll 8
        for (int c = 0; c < 64; c++) {
            float a[4], b[4];
            #pragma unroll
            for (int u = 0; u < 4; u++) a[u] = As[(ty + 16*u)*65 + c];
            #pragma unroll
            for (int v = 0; v < 4; v++) b[v] = Bs[(tx + 16*v)*65 + c];
            #pragma unroll
            for (int u = 0; u < 4; u++)
                #pragma unroll
                for (int v = 0; v < 4; v++) acc[u][v] += a[u]*b[v];
        }
    }
    #pragma unroll
    for (int u = 0; u < 4; u++)
        #pragma unroll
        for (int v = 0; v < 4; v++) {
            int row = bx*64 + ty + 16*u;
            int col = by*64 + tx + 16*v;
            if (col < 1024) g_q[(size_t)row*1024 + col]          = acc[u][v];
            else            g_k[(size_t)row*1024 + (col - 1024)] = acc[u][v];
        }
}

// --------------------------------------------------------- fused attention
// Block = (b, h, i=qt), 512 threads (16 warps). Scores S[q][l*32+k].
// Two key tiles processed concurrently (one per 256-thread half), each half
// owning its own K buffer; gmem latency hidden via register prefetch.
#define SS_OFF 0          // 32*1025 = 32800
#define QS_OFF 32800      // 32*129  = 4128
#define KS_OFF 36928      // 2 * 32*129 = 8256  (one buffer per half)
#define XS_OFF 45184      // 2 * 4096   = 8192
#define RR_OFF 53376      // 1024
#define RC_OFF 54400      // 1024
#define RZ_OFF 55424      // 32
#define SMEM_FLOATS 55456 // *4 = 221824 bytes

__global__ void __launch_bounds__(512, 1) attn_kernel(
    const float* __restrict__ row_emb, const float* __restrict__ col_emb,
    float* __restrict__ probs, int write_probs)
{
    extern __shared__ float sm[];
    float* Ss = sm + SS_OFF;
    float* Qs = sm + QS_OFF;
    float* rr = sm + RR_OFF;
    float* rc = sm + RC_OFF;
    float* rz = sm + RZ_OFF;

    const int qt = blockIdx.x;   // i
    const int h  = blockIdx.y;
    const int b  = blockIdx.z;
    const int t  = threadIdx.x;

    // A: load Q tile (32 queries x 128)
    const float* qbase = g_q + (size_t)b*1048576 + (size_t)qt*32768 + h*128;
    #pragma unroll
    for (int i = 0; i < 8; i++) {
        int e = t + i*512;
        int jq = e >> 7, d = e & 127;
        Qs[jq*129 + d] = qbase[(size_t)jq*1024 + d];
    }
    __syncthreads();

    // B: relative-position terms rr[q][k], rc[q][l]
    #pragma unroll
    for (int i = 0; i < 4; i++) {
        int e = t + i*512;
        if (e < 1024) {
            int jq = e >> 5, k = e & 31;
            const float* er = row_emb + (k - qt + 31)*64;
            const float* qv = Qs + jq*129;
            float s = 0.f;
            #pragma unroll 16
            for (int d = 0; d < 64; d++) s += qv[d]*er[d];
            rr[e] = s;
        } else {
            int e2 = e - 1024;
            int jq = e2 >> 5, l = e2 & 31;
            const float* ec = col_emb + (l - jq + 31)*64;
            const float* qv = Qs + jq*129 + 64;
            float s = 0.f;
            #pragma unroll 16
            for (int d = 0; d < 64; d++) s += qv[d]*ec[d];
            rc[e2] = s;
        }
    }
    __syncthreads();

    // C: init scores with rel terms (layout S[q][l*32+k])
    #pragma unroll
    for (int i = 0; i < 64; i++) {
        int e = t + i*512;
        int q = e >> 10, rem = e & 1023;
        int l = rem >> 5, k = rem & 31;
        Ss[q*1025 + rem] = rr[q*32 + k] + rc[q*32 + l];
    }

    // D: content scores; two lt tiles at a time, one per half.
    // Each half owns buffer KS_OFF + half*4128 (reuse safe: trailing sync
    // separates this iter's reads from next iter's writes).
    {
        const int half = t >> 8;          // 0/1 -> which lt of the pair
        const int tl   = t & 255;
        const int ty = tl >> 4, tx = tl & 15;
        const float* kbase = g_k + (size_t)b*1048576 + h*128;
        float* Kb = sm + KS_OFF + half*4128;
        float kreg[16];
        {   // preload tile lt = half
            int lt = half;
            #pragma unroll
            for (int i = 0; i < 16; i++) {
                int e = tl + i*256;
                kreg[i] = kbase[(size_t)(e >> 7)*32768 + (size_t)lt*1024 + (e & 127)];
            }
        }
        for (int ltp = 0; ltp < 16; ltp++) {
            const int lt = 2*ltp + half;
            #pragma unroll
            for (int i = 0; i < 16; i++) {
                int e = tl + i*256;
                Kb[(e >> 7)*129 + (e & 127)] = kreg[i];
            }
            __syncthreads();
            if (ltp < 15) {
                int ltn = lt + 2;
                #pragma unroll
                for (int i = 0; i < 16; i++) {
                    int e = tl + i*256;
                    kreg[i] = kbase[(size_t)(e >> 7)*32768 + (size_t)ltn*1024 + (e & 127)];
                }
            }
            float a00=0.f, a01=0.f, a10=0.f, a11=0.f;
            const float* Q0 = Qs + (2*ty)*129;
            const float* Q1 = Q0 + 129;
            const float* K0 = Kb + (2*tx)*129;
            const float* K1 = K0 + 129;
            #pragma unroll 16
            for (int d = 0; d < 128; d++) {
                float q0 = Q0[d], q1 = Q1[d], k0 = K0[d], k1 = K1[d];
                a00 += q0*k0; a01 += q0*k1; a10 += q1*k0; a11 += q1*k1;
            }
            int cb = lt*32;
            Ss[(2*ty  )*1025 + cb + 2*tx    ] += a00;
            Ss[(2*ty  )*1025 + cb + 2*tx + 1] += a01;
            Ss[(2*ty+1)*1025 + cb + 2*tx    ] += a10;
            Ss[(2*ty+1)*1025 + cb + 2*tx + 1] += a11;
            __syncthreads();
        }
    }

    // E: softmax — 16 threads per query row
    {
        int q = t >> 4, g = t & 15;
        float* row = Ss + q*1025;
        float m = -1e30f;
        #pragma unroll 8
        for (int mm = 0; mm < 64; mm++) m = fmaxf(m, row[g + 16*mm]);
        m = fmaxf(m, __shfl_xor_sync(0xffffffffu, m, 1));
        m = fmaxf(m, __shfl_xor_sync(0xffffffffu, m, 2));
        m = fmaxf(m, __shfl_xor_sync(0xffffffffu, m, 4));
        m = fmaxf(m, __shfl_xor_sync(0xffffffffu, m, 8));
        float z = 0.f;
        #pragma unroll 8
        for (int mm = 0; mm < 64; mm++) {
            int idx = g + 16*mm;
            float p = __expf(SCALE*(row[idx] - m));
            row[idx] = p;
            z += p;
        }
        z += __shfl_xor_sync(0xffffffffu, z, 1);
        z += __shfl_xor_sync(0xffffffffu, z, 2);
        z += __shfl_xor_sync(0xffffffffu, z, 4);
        z += __shfl_xor_sync(0xffffffffu, z, 8);
        if (g == 0) rz[q] = 1.0f / z;
    }
    __syncthreads();

    // F: write probs (layout [b][j=q][i=qt][h][l][k] — matches smem order)
    if (write_probs) {
        size_t pb0 = ((size_t)(b*1024 + qt) * 8 + h) * 1024;
        #pragma unroll
        for (int i = 0; i < 64; i++) {
            int e = t + i*512;
            int q = e >> 10, off = e & 1023;
            probs[pb0 + (size_t)q*262144 + off] = Ss[q*1025 + off] * rz[q];
        }
    }

    // G: context = P @ X, X tiles double-buffered with register prefetch
    {
        const int q = t & 31, dc = t >> 5;     // dc in [0,16): 8 d-elems each
        float acc[8];
        #pragma unroll
        for (int u = 0; u < 8; u++) acc[u] = 0.f;
        const float4* xb4 = (const float4*)(g_x + (size_t)b*131072);
        float4 xreg0 = xb4[t], xreg1 = xb4[t + 512];   // preload lt=0
        for (int lt = 0; lt < 32; lt++) {
            float* Xb = sm + XS_OFF + (lt & 1)*4096;
            ((float4*)Xb)[t]       = xreg0;
            ((float4*)Xb)[t + 512] = xreg1;
            __syncthreads();
            if (lt < 31) {
                xreg0 = xb4[(lt+1)*1024 + t];
                xreg1 = xb4[(lt+1)*1024 + t + 512];
            }
            const float* Prow = Ss + q*1025 + lt*32;
            #pragma unroll 4
            for (int kk = 0; kk < 32; kk++) {
                float p = Prow[kk];
                const float4* xv = (const float4*)(Xb + kk*128 + dc*8);
                float4 x0 = xv[0], x1 = xv[1];
                acc[0] += p*x0.x; acc[1] += p*x0.y; acc[2] += p*x0.z; acc[3] += p*x0.w;
                acc[4] += p*x1.x; acc[5] += p*x1.y; acc[6] += p*x1.z; acc[7] += p*x1.w;
            }
            __syncthreads();
        }
        float s = rz[q];
        float* ob = g_ctx + ((size_t)(b*1024 + q*32 + qt))*1024 + h*128 + dc*8;
        #pragma unroll
        for (int u = 0; u < 8; u++) ob[u] = acc[u]*s;
    }
}

// ------------------------------------------ output projection + bias + residual
// 32-row tiles -> grid 256 (2 CTAs/SM)
__global__ void __launch_bounds__(256) out_kernel(const float* __restrict__ Wv,
                                                  const float* __restrict__ bv,
                                                  float* __restrict__ out) {
    __shared__ float As[32*33];
    __shared__ float Bs[128*33];
    int bx = blockIdx.x;              // 256 row tiles of 32
    int t = threadIdx.x, ty = t >> 5, tx = t & 31;   // ty 0..7, tx 0..31
    float acc[4][4] = {};
    for (int ct = 0; ct < 32; ct++) {
        __syncthreads();
        #pragma unroll
        for (int i = 0; i < 4; i++) {
            int e = t + i*256;
            int r = e >> 5, c = e & 31;
            As[r*33 + c] = g_ctx[(size_t)(bx*32 + r)*1024 + ct*32 + c];
        }
        #pragma unroll
        for (int i = 0; i < 16; i++) {
            int e = t + i*256;
            int o = e >> 5, c = e & 31;
            Bs[o*33 + c] = Wv[(size_t)o*1024 + ct*32 + c];
        }
        __syncthreads();
        #pragma unroll 8
        for (int c = 0; c < 32; c++) {
            float a[4], bb[4];
            #pragma unroll
            for (int u = 0; u < 4; u++) a[u] = As[(ty + 8*u)*33 + c];
            #pragma unroll
            for (int v = 0; v < 4; v++) bb[v] = Bs[(tx + 32*v)*33 + c];
            #pragma unroll
            for (int u = 0; u < 4; u++)
                #pragma unroll
                for (int v = 0; v < 4; v++) acc[u][v] += a[u]*bb[v];
        }
    }
    #pragma unroll
    for (int u = 0; u < 4; u++)
        #pragma unroll
        for (int v = 0; v < 4; v++) {
            int r = bx*32 + ty + 8*u;
            int o = tx + 32*v;
            out[(size_t)r*128 + o] = acc[u][v] + bv[o] + g_x[(size_t)r*128 + o];
        }
}

// ---------------------------------------------------------------- launcher
extern "C" void kernel_launch(void* const* d_in, const int* in_sizes, int n_in,
                              void* d_out, int out_size) {
    const float* hs      = (const float*)d_in[0];
    const float* row_emb = (const float*)d_in[1];
    const float* col_emb = (const float*)d_in[2];
    const float* Wq      = (const float*)d_in[3];
    const float* Wk      = (const float*)d_in[4];
    const float* Wv      = (const float*)d_in[5];
    const float* bv      = (const float*)d_in[6];
    const float* ln_g    = (const float*)d_in[7];
    const float* ln_b    = (const float*)d_in[8];
    float* out = (float*)d_out;

    // output tensor = 1,048,576 floats; probs = 67,108,864 floats
    int write_probs = (out_size >= 1048576 + 67108864) ? 1 : 0;
    float* probs = write_probs ? (out + 1048576) : out;

    cudaFuncSetAttribute(attn_kernel, cudaFuncAttributeMaxDynamicSharedMemorySize,
                         SMEM_FLOATS * 4);

    ln_kernel<<<8192, 128>>>(hs, ln_g, ln_b);

    dim3 gqk(128, 32);
    qk_kernel<<<gqk, 256>>>(Wq, Wk);

    dim3 gat(32, NHEADS, BSZ);
    attn_kernel<<<gat, 512, SMEM_FLOATS * 4>>>(row_emb, col_emb, probs, write_probs);

    out_kernel<<<256, 256>>>(Wv, bv, out);
}

// round 9
// speedup vs baseline: 1.6116x; 1.1406x over previous
#include <cuda_runtime.h>
#include <cuda_bf16.h>
#include <math.h>
#include <stdint.h>

// Problem constants
#define BSZ 8
#define HW 32
#define DMODEL 128
#define NHEADS 8
#define SCALE 0.08838834764831845f   // 1/sqrt(128)

// ---------------------------------------------------------------- scratch
__device__ float g_x  [BSZ*HW*HW*DMODEL];            // LN output  (4 MB)
__device__ float g_q  [BSZ*HW*HW*NHEADS*DMODEL];     // 32 MB
__device__ float g_k  [BSZ*HW*HW*NHEADS*DMODEL];     // 32 MB
__device__ float g_ctx[BSZ*HW*HW*NHEADS*DMODEL];     // 32 MB
__device__ __nv_bfloat16 g_xth[BSZ*DMODEL*1024];     // x^T hi  (2 MB)  [b][d][n]
__device__ __nv_bfloat16 g_xtl[BSZ*DMODEL*1024];     // x^T lo  (2 MB)
__device__ float g_rz [BSZ*NHEADS*1024];             // 1/z per score row
__device__ float g_pscratch[67108864];               // fallback probs buffer

// fp32 pair -> bf16x2 (hi) + bf16x2 (residual lo)
__device__ __forceinline__ void split_pair(float x, float y, uint32_t& hi, uint32_t& lo) {
    __nv_bfloat16 hx = __float2bfloat16(x), hy = __float2bfloat16(y);
    float rx = x - __bfloat162float(hx), ry = y - __bfloat162float(hy);
    __nv_bfloat162 H; H.x = hx; H.y = hy;
    __nv_bfloat162 L; L.x = __float2bfloat16(rx); L.y = __float2bfloat16(ry);
    hi = *reinterpret_cast<uint32_t*>(&H);
    lo = *reinterpret_cast<uint32_t*>(&L);
}

// warp-level bf16 MMA, m16n8k16, fp32 accumulate (base PTX; works on sm_100)
__device__ __forceinline__ void mma_bf16(float* d, const uint32_t* a, const uint32_t* b) {
    asm volatile(
        "mma.sync.aligned.m16n8k16.row.col.f32.bf16.bf16.f32 "
        "{%0,%1,%2,%3}, {%4,%5,%6,%7}, {%8,%9}, {%0,%1,%2,%3};"
        : "+f"(d[0]), "+f"(d[1]), "+f"(d[2]), "+f"(d[3])
        : "r"(a[0]), "r"(a[1]), "r"(a[2]), "r"(a[3]), "r"(b[0]), "r"(b[1]));
}

// ---------------------------------------------------------------- LayerNorm
__global__ void ln_kernel(const float* __restrict__ hs,
                          const float* __restrict__ gam,
                          const float* __restrict__ bet) {
    int row = blockIdx.x;          // 8192 rows
    int c   = threadIdx.x;         // 128
    float v = hs[row*128 + c];
    float s = v, s2 = v*v;
    #pragma unroll
    for (int o = 16; o >= 1; o >>= 1) {
        s  += __shfl_xor_sync(0xffffffffu, s,  o);
        s2 += __shfl_xor_sync(0xffffffffu, s2, o);
    }
    __shared__ float ws[4], ws2[4];
    int w = c >> 5;
    if ((c & 31) == 0) { ws[w] = s; ws2[w] = s2; }
    __syncthreads();
    s  = ws[0] + ws[1] + ws[2] + ws[3];
    s2 = ws2[0] + ws2[1] + ws2[2] + ws2[3];
    float mu  = s  * (1.0f/128.0f);
    float var = s2 * (1.0f/128.0f) - mu*mu;
    float r   = rsqrtf(var + 1e-5f);
    g_x[row*128 + c] = (v - mu) * r * gam[c] + bet[c];
}

// -------------------------------------------- x transpose -> bf16 hi/lo [b][d][n]
__global__ void __launch_bounds__(256) xt_kernel() {
    __shared__ float sm[32][33];
    int nt = blockIdx.x, dt = blockIdx.y, b = blockIdx.z;
    int t = threadIdx.x;
    #pragma unroll
    for (int it = 0; it < 4; it++) {
        int tn = (t >> 5) + it*8, td = t & 31;
        sm[tn][td] = g_x[((size_t)b*1024 + nt*32 + tn)*128 + dt*32 + td];
    }
    __syncthreads();
    #pragma unroll
    for (int it = 0; it < 2; it++) {
        int w = t + it*256;
        int td = w >> 4, np = w & 15;
        uint32_t hi, lo;
        split_pair(sm[2*np][td], sm[2*np+1][td], hi, lo);
        size_t off = ((size_t)b*128 + dt*32 + td)*1024 + nt*32 + 2*np;
        *reinterpret_cast<uint32_t*>(&g_xth[off]) = hi;
        *reinterpret_cast<uint32_t*>(&g_xtl[off]) = lo;
    }
}

// ------------------------------------------------- fused Q,K projection GEMM
__global__ void __launch_bounds__(256) qk_kernel(const float* __restrict__ Wq,
                                                 const float* __restrict__ Wk) {
    __shared__ float As[64*65];
    __shared__ float Bs[64*65];
    int bx = blockIdx.x;           // 128 row tiles of 64
    int by = blockIdx.y;           // 32 col tiles of 64
    int t  = threadIdx.x;
    int ty = t >> 4, tx = t & 15;
    float acc[4][4] = {};
    for (int kt = 0; kt < 2; kt++) {
        __syncthreads();
        for (int e = t; e < 64*64; e += 256) {
            int r = e >> 6, c = e & 63;
            As[r*65 + c] = g_x[(bx*64 + r)*128 + kt*64 + c];
            int o = by*64 + r;
            const float* W = (o < 1024) ? (Wq + o*128) : (Wk + (o-1024)*128);
            Bs[r*65 + c] = W[kt*64 + c];
        }
        __syncthreads();
        #pragma unroll 8
        for (int c = 0; c < 64; c++) {
            float a[4], b[4];
            #pragma unroll
            for (int u = 0; u < 4; u++) a[u] = As[(ty + 16*u)*65 + c];
            #pragma unroll
            for (int v = 0; v < 4; v++) b[v] = Bs[(tx + 16*v)*65 + c];
            #pragma unroll
            for (int u = 0; u < 4; u++)
                #pragma unroll
                for (int v = 0; v < 4; v++) acc[u][v] += a[u]*b[v];
        }
    }
    #pragma unroll
    for (int u = 0; u < 4; u++)
        #pragma unroll
        for (int v = 0; v < 4; v++) {
            int row = bx*64 + ty + 16*u;
            int col = by*64 + tx + 16*v;
            if (col < 1024) g_q[(size_t)row*1024 + col]          = acc[u][v];
            else            g_k[(size_t)row*1024 + (col - 1024)] = acc[u][v];
        }
}

// ================================================ mma.sync scores + exp kernel
// CTA = (mt, h, b): 128 score rows, 1024 cols in 8 chunks of 128.
// S = Q·K^T via bf16 hi/lo (3 chains). Unnormalized exp -> P, 1/z -> g_rz.
// smem uint32 tiles [row*65 + k2] (k2 = k/2), conflict-free padding.
#define SC_QH   0
#define SC_QL   33280
#define SC_KH   66560
#define SC_KL   99840
#define SC_RR   133120
#define SC_RC   149504
#define SC_SMEM 165888

__global__ void __launch_bounds__(256, 1)
scores_kernel(const float* __restrict__ row_emb, const float* __restrict__ col_emb,
              float* __restrict__ P)
{
    extern __shared__ char smc[];
    uint32_t* QH = (uint32_t*)(smc + SC_QH);
    uint32_t* QL = (uint32_t*)(smc + SC_QL);
    uint32_t* KH = (uint32_t*)(smc + SC_KH);
    uint32_t* KL = (uint32_t*)(smc + SC_KL);
    float*    RR = (float*)(smc + SC_RR);
    float*    RC = (float*)(smc + SC_RC);

    const int t = threadIdx.x;
    const int wid = t >> 5, lane = t & 31;
    const int gid = lane >> 2, tig = lane & 3;
    const int wrow = wid * 16;               // warp's 16 m-rows
    const int mt = blockIdx.x, h = blockIdx.y, b = blockIdx.z;

    const float* qb = g_q + ((size_t)b*1024 + mt*128)*1024 + h*128;

    // Q tile -> smem hi/lo
    for (int w = t; w < 8192; w += 256) {
        int row = w >> 6, k2 = w & 63;
        float2 v = *(const float2*)(qb + (size_t)row*1024 + k2*2);
        uint32_t hi, lo; split_pair(v.x, v.y, hi, lo);
        QH[row*65 + k2] = hi; QL[row*65 + k2] = lo;
    }
    // relative-position terms
    for (int w = t; w < 8192; w += 256) {
        if (w < 4096) {
            int row = w >> 5, k = w & 31;
            int ig = (mt*128 + row) >> 5;
            const float* e  = row_emb + (k - ig + 31)*64;
            const float* qv = qb + (size_t)row*1024;
            float s = 0.f;
            #pragma unroll 16
            for (int d = 0; d < 64; d++) s += qv[d]*e[d];
            RR[row*32 + k] = s;
        } else {
            int w2 = w - 4096;
            int row = w2 >> 5, l = w2 & 31;
            int jg = (mt*128 + row) & 31;
            const float* e  = col_emb + (l - jg + 31)*64;
            const float* qv = qb + (size_t)row*1024 + 64;
            float s = 0.f;
            #pragma unroll 16
            for (int d = 0; d < 64; d++) s += qv[d]*e[d];
            RC[row*32 + l] = s;
        }
    }

    const float* kb = g_k + (size_t)b*1024*1024 + h*128;
    const int r0 = wrow + gid;               // fragment row 0 (m)
    const int r1 = r0 + 8;
    // P row pointers (rows fixed across chunks)
    const int rg0 = mt*128 + r0, rg1 = mt*128 + r1;
    float* prow0 = P + ((((size_t)b*32 + (rg0 & 31))*32 + (rg0 >> 5))*8 + h)*1024;
    float* prow1 = P + ((((size_t)b*32 + (rg1 & 31))*32 + (rg1 >> 5))*8 + h)*1024;
    float z0 = 0.f, z1 = 0.f;

    for (int c = 0; c < 8; c++) {
        __syncthreads();   // previous chunk's fragment loads done before K overwrite
        for (int w = t; w < 8192; w += 256) {
            int np = w >> 6, k2 = w & 63;
            int n = c*128 + np;
            int src = (n & 31)*32 + (n >> 5);
            float2 v = *(const float2*)(kb + (size_t)src*1024 + k2*2);
            uint32_t hi, lo; split_pair(v.x, v.y, hi, lo);
            KH[np*65 + k2] = hi; KL[np*65 + k2] = lo;
        }
        __syncthreads();

        float acc[16][4];
        #pragma unroll
        for (int nt = 0; nt < 16; nt++)
            #pragma unroll
            for (int u = 0; u < 4; u++) acc[nt][u] = 0.f;

        #pragma unroll
        for (int ks = 0; ks < 8; ks++) {
            uint32_t aH[4], aL[4];
            int ca = 8*ks + tig;
            aH[0] = QH[r0*65 + ca];     aH[1] = QH[r1*65 + ca];
            aH[2] = QH[r0*65 + ca + 4]; aH[3] = QH[r1*65 + ca + 4];
            aL[0] = QL[r0*65 + ca];     aL[1] = QL[r1*65 + ca];
            aL[2] = QL[r0*65 + ca + 4]; aL[3] = QL[r1*65 + ca + 4];
            #pragma unroll
            for (int nt = 0; nt < 16; nt++) {
                uint32_t bH[2], bL[2];
                int nb = (8*nt + gid)*65 + 8*ks + tig;
                bH[0] = KH[nb]; bH[1] = KH[nb + 4];
                bL[0] = KL[nb]; bL[1] = KL[nb + 4];
                mma_bf16(acc[nt], aH, bH);
                mma_bf16(acc[nt], aH, bL);
                mma_bf16(acc[nt], aL, bH);
            }
        }

        // epilogue: +rel, exp, accumulate z, store unnormalized probs
        #pragma unroll
        for (int nt = 0; nt < 16; nt++) {
            int cn = 8*nt + 2*tig;           // local col of first element
            int cg = c*128 + cn;             // global col
            int l = cg >> 5;
            int k0 = cg & 31, k1 = (cg + 1) & 31;
            float rc0r0 = RC[r0*32 + l], rc0r1 = RC[r1*32 + l];
            float p00 = __expf(SCALE*(acc[nt][0] + RR[r0*32 + k0] + rc0r0));
            float p01 = __expf(SCALE*(acc[nt][1] + RR[r0*32 + k1] + rc0r0));
            float p10 = __expf(SCALE*(acc[nt][2] + RR[r1*32 + k0] + rc0r1));
            float p11 = __expf(SCALE*(acc[nt][3] + RR[r1*32 + k1] + rc0r1));
            z0 += p00 + p01;
            z1 += p10 + p11;
            *(float2*)(prow0 + cg) = make_float2(p00, p01);
            *(float2*)(prow1 + cg) = make_float2(p10, p11);
        }
    }

    // reduce z across the 4 lanes of each row group, write 1/z
    z0 += __shfl_xor_sync(0xffffffffu, z0, 1);
    z0 += __shfl_xor_sync(0xffffffffu, z0, 2);
    z1 += __shfl_xor_sync(0xffffffffu, z1, 1);
    z1 += __shfl_xor_sync(0xffffffffu, z1, 2);
    if (tig == 0) {
        g_rz[((size_t)b*8 + h)*1024 + rg0] = 1.0f / z0;
        g_rz[((size_t)b*8 + h)*1024 + rg1] = 1.0f / z1;
    }
}

// ---------------------------------------- normalize probs in place (P *= rz)
__global__ void __launch_bounds__(256) norm_kernel(float* __restrict__ P) {
    size_t i4 = (size_t)blockIdx.x*256 + threadIdx.x;   // 16,777,216 float4s
    size_t e = i4 * 4;
    int hh = (int)((e >> 10) & 7);
    int ii = (int)((e >> 13) & 31);
    int jj = (int)((e >> 18) & 31);
    int bb = (int)(e >> 23);
    float rz = g_rz[(((size_t)bb*8 + hh) << 10) + ii*32 + jj];
    float4 v = ((float4*)P)[i4];
    v.x *= rz; v.y *= rz; v.z *= rz; v.w *= rz;
    ((float4*)P)[i4] = v;
}

// ================================================ mma.sync context GEMM kernel
// CTA = (mt, h, b): ctx rows r2 in [mt*128, +128); ctx = P(128x1024) x X^T,
// fp32 accumulate in registers over 8 seq-chunks.
#define CT_AH   0
#define CT_AL   33280
#define CT_BH   66560
#define CT_BL   99840
#define CT_SMEM 133120

__global__ void __launch_bounds__(256, 1)
ctx_kernel(const float* __restrict__ P)
{
    extern __shared__ char smc[];
    uint32_t* AH = (uint32_t*)(smc + CT_AH);
    uint32_t* AL = (uint32_t*)(smc + CT_AL);
    uint32_t* BH = (uint32_t*)(smc + CT_BH);
    uint32_t* BL = (uint32_t*)(smc + CT_BL);

    const int t = threadIdx.x;
    const int wid = t >> 5, lane = t & 31;
    const int gid = lane >> 2, tig = lane & 3;
    const int wrow = wid * 16;
    const int mt = blockIdx.x, h = blockIdx.y, b = blockIdx.z;

    const uint32_t* xh = (const uint32_t*)g_xth;
    const uint32_t* xl = (const uint32_t*)g_xtl;

    float acc[16][4];
    #pragma unroll
    for (int nt = 0; nt < 16; nt++)
        #pragma unroll
        for (int u = 0; u < 4; u++) acc[nt][u] = 0.f;

    const int r0 = wrow + gid, r1 = r0 + 8;

    for (int c = 0; c < 8; c++) {
        __syncthreads();
        // A = normalized probs rows (fp32 -> hi/lo)
        for (int w = t; w < 8192; w += 256) {
            int m = w >> 6, k2 = w & 63;
            int r2 = mt*128 + m;
            const float* arow = P + ((((size_t)b*32 + (r2 >> 5))*32 + (r2 & 31))*8 + h)*1024 + c*128;
            float2 v = *(const float2*)(arow + k2*2);
            uint32_t hi, lo; split_pair(v.x, v.y, hi, lo);
            AH[m*65 + k2] = hi; AL[m*65 + k2] = lo;
        }
        // B = x^T (bf16 hi/lo, [b][d][n])
        for (int w = t; w < 8192; w += 256) {
            int dp = w >> 6, k2 = w & 63;
            size_t idx = ((size_t)b*128 + dp)*512 + c*64 + k2;   // uint32 units
            BH[dp*65 + k2] = xh[idx];
            BL[dp*65 + k2] = xl[idx];
        }
        __syncthreads();

        #pragma unroll
        for (int ks = 0; ks < 8; ks++) {
            uint32_t aH[4], aL[4];
            int ca = 8*ks + tig;
            aH[0] = AH[r0*65 + ca];     aH[1] = AH[r1*65 + ca];
            aH[2] = AH[r0*65 + ca + 4]; aH[3] = AH[r1*65 + ca + 4];
            aL[0] = AL[r0*65 + ca];     aL[1] = AL[r1*65 + ca];
            aL[2] = AL[r0*65 + ca + 4]; aL[3] = AL[r1*65 + ca + 4];
            #pragma unroll
            for (int nt = 0; nt < 16; nt++) {
                uint32_t bH[2], bL[2];
                int nb = (8*nt + gid)*65 + 8*ks + tig;
                bH[0] = BH[nb]; bH[1] = BH[nb + 4];
                bL[0] = BL[nb]; bL[1] = BL[nb + 4];
                mma_bf16(acc[nt], aH, bH);
                mma_bf16(acc[nt], aH, bL);
                mma_bf16(acc[nt], aL, bH);
            }
        }
    }

    // epilogue: write g_ctx rows r2 = mt*128 + {r0, r1}
    {
        int r2a = mt*128 + r0, r2b = mt*128 + r1;
        float* oa = g_ctx + ((size_t)b*1024 + r2a)*1024 + h*128;
        float* ob = g_ctx + ((size_t)b*1024 + r2b)*1024 + h*128;
        #pragma unroll
        for (int nt = 0; nt < 16; nt++) {
            int cn = 8*nt + 2*tig;
            *(float2*)(oa + cn) = make_float2(acc[nt][0], acc[nt][1]);
            *(float2*)(ob + cn) = make_float2(acc[nt][2], acc[nt][3]);
        }
    }
}

// ------------------------------------------ output projection + bias + residual
__global__ void __launch_bounds__(256) out_kernel(const float* __restrict__ Wv,
                                                  const float* __restrict__ bv,
                                                  float* __restrict__ out) {
    __shared__ float As[32*33];
    __shared__ float Bs[128*33];
    int bx = blockIdx.x;              // 256 row tiles of 32
    int t = threadIdx.x, ty = t >> 5, tx = t & 31;
    float acc[4][4] = {};
    for (int ct = 0; ct < 32; ct++) {
        __syncthreads();
        #pragma unroll
        for (int i = 0; i < 4; i++) {
            int e = t + i*256;
            int r = e >> 5, c = e & 31;
            As[r*33 + c] = g_ctx[(size_t)(bx*32 + r)*1024 + ct*32 + c];
        }
        #pragma unroll
        for (int i = 0; i < 16; i++) {
            int e = t + i*256;
            int o = e >> 5, c = e & 31;
            Bs[o*33 + c] = Wv[(size_t)o*1024 + ct*32 + c];
        }
        __syncthreads();
        #pragma unroll 8
        for (int c = 0; c < 32; c++) {
            float a[4], bb[4];
            #pragma unroll
            for (int u = 0; u < 4; u++) a[u] = As[(ty + 8*u)*33 + c];
            #pragma unroll
            for (int v = 0; v < 4; v++) bb[v] = Bs[(tx + 32*v)*33 + c];
            #pragma unroll
            for (int u = 0; u < 4; u++)
                #pragma unroll
                for (int v = 0; v < 4; v++) acc[u][v] += a[u]*bb[v];
        }
    }
    #pragma unroll
    for (int u = 0; u < 4; u++)
        #pragma unroll
        for (int v = 0; v < 4; v++) {
            int r = bx*32 + ty + 8*u;
            int o = tx + 32*v;
            out[(size_t)r*128 + o] = acc[u][v] + bv[o] + g_x[(size_t)r*128 + o];
        }
}

// ---------------------------------------------------------------- launcher
extern "C" void kernel_launch(void* const* d_in, const int* in_sizes, int n_in,
                              void* d_out, int out_size) {
    const float* hs      = (const float*)d_in[0];
    const float* row_emb = (const float*)d_in[1];
    const float* col_emb = (const float*)d_in[2];
    const float* Wq      = (const float*)d_in[3];
    const float* Wk      = (const float*)d_in[4];
    const float* Wv      = (const float*)d_in[5];
    const float* bv      = (const float*)d_in[6];
    const float* ln_g    = (const float*)d_in[7];
    const float* ln_b    = (const float*)d_in[8];
    float* out = (float*)d_out;

    int write_probs = (out_size >= 1048576 + 67108864) ? 1 : 0;
    float* P;
    if (write_probs) {
        P = out + 1048576;
    } else {
        cudaGetSymbolAddress((void**)&P, g_pscratch);
    }

    cudaFuncSetAttribute(scores_kernel, cudaFuncAttributeMaxDynamicSharedMemorySize, SC_SMEM);
    cudaFuncSetAttribute(ctx_kernel,    cudaFuncAttributeMaxDynamicSharedMemorySize, CT_SMEM);

    ln_kernel<<<8192, 128>>>(hs, ln_g, ln_b);

    dim3 gxt(32, 4, BSZ);
    xt_kernel<<<gxt, 256>>>();

    dim3 gqk(128, 32);
    qk_kernel<<<gqk, 256>>>(Wq, Wk);

    dim3 gsc(8, NHEADS, BSZ);
    scores_kernel<<<gsc, 256, SC_SMEM>>>(row_emb, col_emb, P);

    norm_kernel<<<65536, 256>>>(P);

    dim3 gct(8, NHEADS, BSZ);
    ctx_kernel<<<gct, 256, CT_SMEM>>>(P);

    out_kernel<<<256, 256>>>(Wv, bv, out);
}

// round 11
// speedup vs baseline: 2.4382x; 1.5129x over previous
#include <cuda_runtime.h>
#include <cuda_bf16.h>
#include <math.h>
#include <stdint.h>

// Problem constants
#define BSZ 8
#define HW 32
#define DMODEL 128
#define NHEADS 8
#define SCALE 0.08838834764831845f   // 1/sqrt(128)
#define PS 68                         // smem row stride in uint32 (conflict-free: bank=4*gid+tig)

// ---------------------------------------------------------------- scratch
__device__ float g_x  [BSZ*HW*HW*DMODEL];            // LN output  (4 MB)
__device__ float g_q  [BSZ*HW*HW*NHEADS*DMODEL];     // 32 MB
__device__ float g_k  [BSZ*HW*HW*NHEADS*DMODEL];     // 32 MB
__device__ float g_ctx[BSZ*HW*HW*NHEADS*DMODEL];     // 32 MB
__device__ __nv_bfloat16 g_xth[BSZ*DMODEL*1024];     // x^T hi  (2 MB)  [b][d][n]
__device__ __nv_bfloat16 g_xtl[BSZ*DMODEL*1024];     // x^T lo  (2 MB)
__device__ float g_rz [BSZ*NHEADS*1024];             // 1/z per score row
__device__ float g_pscratch[67108864];               // fallback probs buffer

// fp32 pair -> bf16x2 (hi) + bf16x2 (residual lo)
__device__ __forceinline__ void split_pair(float x, float y, uint32_t& hi, uint32_t& lo) {
    __nv_bfloat16 hx = __float2bfloat16(x), hy = __float2bfloat16(y);
    float rx = x - __bfloat162float(hx), ry = y - __bfloat162float(hy);
    __nv_bfloat162 H; H.x = hx; H.y = hy;
    __nv_bfloat162 L; L.x = __float2bfloat16(rx); L.y = __float2bfloat16(ry);
    hi = *reinterpret_cast<uint32_t*>(&H);
    lo = *reinterpret_cast<uint32_t*>(&L);
}

// warp-level bf16 MMA, m16n8k16, fp32 accumulate (base PTX; works on sm_100)
__device__ __forceinline__ void mma_bf16(float* d, const uint32_t* a, const uint32_t* b) {
    asm volatile(
        "mma.sync.aligned.m16n8k16.row.col.f32.bf16.bf16.f32 "
        "{%0,%1,%2,%3}, {%4,%5,%6,%7}, {%8,%9}, {%0,%1,%2,%3};"
        : "+f"(d[0]), "+f"(d[1]), "+f"(d[2]), "+f"(d[3])
        : "r"(a[0]), "r"(a[1]), "r"(a[2]), "r"(a[3]), "r"(b[0]), "r"(b[1]));
}

// ---------------------------------------------------------------- LayerNorm
__global__ void ln_kernel(const float* __restrict__ hs,
                          const float* __restrict__ gam,
                          const float* __restrict__ bet) {
    int row = blockIdx.x;          // 8192 rows
    int c   = threadIdx.x;         // 128
    float v = hs[row*128 + c];
    float s = v, s2 = v*v;
    #pragma unroll
    for (int o = 16; o >= 1; o >>= 1) {
        s  += __shfl_xor_sync(0xffffffffu, s,  o);
        s2 += __shfl_xor_sync(0xffffffffu, s2, o);
    }
    __shared__ float ws[4], ws2[4];
    int w = c >> 5;
    if ((c & 31) == 0) { ws[w] = s; ws2[w] = s2; }
    __syncthreads();
    s  = ws[0] + ws[1] + ws[2] + ws[3];
    s2 = ws2[0] + ws2[1] + ws2[2] + ws2[3];
    float mu  = s  * (1.0f/128.0f);
    float var = s2 * (1.0f/128.0f) - mu*mu;
    float r   = rsqrtf(var + 1e-5f);
    g_x[row*128 + c] = (v - mu) * r * gam[c] + bet[c];
}

// -------------------------------------------- x transpose -> bf16 hi/lo [b][d][n]
__global__ void __launch_bounds__(256) xt_kernel() {
    __shared__ float sm[32][33];
    int nt = blockIdx.x, dt = blockIdx.y, b = blockIdx.z;
    int t = threadIdx.x;
    #pragma unroll
    for (int it = 0; it < 4; it++) {
        int tn = (t >> 5) + it*8, td = t & 31;
        sm[tn][td] = g_x[((size_t)b*1024 + nt*32 + tn)*128 + dt*32 + td];
    }
    __syncthreads();
    #pragma unroll
    for (int it = 0; it < 2; it++) {
        int w = t + it*256;
        int td = w >> 4, np = w & 15;
        uint32_t hi, lo;
        split_pair(sm[2*np][td], sm[2*np+1][td], hi, lo);
        size_t off = ((size_t)b*128 + dt*32 + td)*1024 + nt*32 + 2*np;
        *reinterpret_cast<uint32_t*>(&g_xth[off]) = hi;
        *reinterpret_cast<uint32_t*>(&g_xtl[off]) = lo;
    }
}

// ================================================ tensorized Q,K projection
// CTA = (bx row-tile of 128, by col-tile of 128). K=128 (one pass).
#define QK_AH   0
#define QK_AL   34816
#define QK_BH   69632
#define QK_BL   104448
#define QK_SMEM 139264

__global__ void __launch_bounds__(512, 1)
qk_mma_kernel(const float* __restrict__ Wq, const float* __restrict__ Wk) {
    extern __shared__ char smc[];
    uint32_t* AH = (uint32_t*)(smc + QK_AH);
    uint32_t* AL = (uint32_t*)(smc + QK_AL);
    uint32_t* BH = (uint32_t*)(smc + QK_BH);
    uint32_t* BL = (uint32_t*)(smc + QK_BL);
    const int t = threadIdx.x;
    const int wid = t >> 5, lane = t & 31;
    const int gid = lane >> 2, tig = lane & 3;
    const int rowgrp = wid & 7, colhalf = wid >> 3;
    const int bx = blockIdx.x, by = blockIdx.y;

    // A = x rows, B = W rows (Wq for by<8, Wk else)
    #pragma unroll
    for (int i = 0; i < 16; i++) {
        int w = t + i*512;
        int row = w >> 6, k2 = w & 63;
        float2 va = *(const float2*)(g_x + (size_t)(bx*128 + row)*128 + k2*2);
        uint32_t hi, lo; split_pair(va.x, va.y, hi, lo);
        AH[row*PS + k2] = hi; AL[row*PS + k2] = lo;
        int o = by*128 + row;
        const float* wr = (o < 1024) ? (Wq + (size_t)o*128) : (Wk + (size_t)(o-1024)*128);
        float2 vb = *(const float2*)(wr + k2*2);
        split_pair(vb.x, vb.y, hi, lo);
        BH[row*PS + k2] = hi; BL[row*PS + k2] = lo;
    }
    __syncthreads();

    const int r0 = rowgrp*16 + gid, r1 = r0 + 8;
    float acc[8][4];
    #pragma unroll
    for (int n = 0; n < 8; n++)
        #pragma unroll
        for (int u = 0; u < 4; u++) acc[n][u] = 0.f;

    #pragma unroll
    for (int ks = 0; ks < 8; ks++) {
        uint32_t aH[4], aL[4];
        int ca = 8*ks + tig;
        aH[0] = AH[r0*PS + ca];     aH[1] = AH[r1*PS + ca];
        aH[2] = AH[r0*PS + ca + 4]; aH[3] = AH[r1*PS + ca + 4];
        aL[0] = AL[r0*PS + ca];     aL[1] = AL[r1*PS + ca];
        aL[2] = AL[r0*PS + ca + 4]; aL[3] = AL[r1*PS + ca + 4];
        #pragma unroll
        for (int n = 0; n < 8; n++) {
            int nt = colhalf*8 + n;
            uint32_t bH[2], bL[2];
            int nb = (8*nt + gid)*PS + ca;
            bH[0] = BH[nb]; bH[1] = BH[nb + 4];
            bL[0] = BL[nb]; bL[1] = BL[nb + 4];
            mma_bf16(acc[n], aH, bH);
            mma_bf16(acc[n], aH, bL);
            mma_bf16(acc[n], aL, bH);
        }
    }

    // epilogue
    #pragma unroll
    for (int n = 0; n < 8; n++) {
        int nt = colhalf*8 + n;
        int cn = 8*nt + 2*tig;
        int colg = by*128 + cn;
        size_t ra = (size_t)(bx*128 + r0), rb = (size_t)(bx*128 + r1);
        if (by < 8) {
            *(float2*)(g_q + ra*1024 + colg)          = make_float2(acc[n][0], acc[n][1]);
            *(float2*)(g_q + rb*1024 + colg)          = make_float2(acc[n][2], acc[n][3]);
        } else {
            *(float2*)(g_k + ra*1024 + (colg - 1024)) = make_float2(acc[n][0], acc[n][1]);
            *(float2*)(g_k + rb*1024 + (colg - 1024)) = make_float2(acc[n][2], acc[n][3]);
        }
    }
}

// ================================================ mma.sync scores + exp kernel
// CTA = (mt, h, b), 512 threads / 16 warps. warp: rows (wid&7)*16..+16,
// cols (wid>>3)*64..+64 of each 128-col chunk. K-chunk double-buffered in regs.
#define SC_QH   0
#define SC_QL   34816
#define SC_KH   69632
#define SC_KL   104448
#define SC_RR   139264
#define SC_RC   155648
#define SC_ZP   172032
#define SC_SMEM 173056

__global__ void __launch_bounds__(512, 1)
scores_kernel(const float* __restrict__ row_emb, const float* __restrict__ col_emb,
              float* __restrict__ P)
{
    extern __shared__ char smc[];
    uint32_t* QH = (uint32_t*)(smc + SC_QH);
    uint32_t* QL = (uint32_t*)(smc + SC_QL);
    uint32_t* KH = (uint32_t*)(smc + SC_KH);
    uint32_t* KL = (uint32_t*)(smc + SC_KL);
    float*    RR = (float*)(smc + SC_RR);
    float*    RC = (float*)(smc + SC_RC);
    float*    ZP = (float*)(smc + SC_ZP);

    const int t = threadIdx.x;
    const int wid = t >> 5, lane = t & 31;
    const int gid = lane >> 2, tig = lane & 3;
    const int rowgrp = wid & 7, colhalf = wid >> 3;
    const int mt = blockIdx.x, h = blockIdx.y, b = blockIdx.z;

    const float* qb = g_q + ((size_t)b*1024 + mt*128)*1024 + h*128;

    // Q tile -> smem hi/lo
    #pragma unroll
    for (int i = 0; i < 16; i++) {
        int w = t + i*512;
        int row = w >> 6, k2 = w & 63;
        float2 v = *(const float2*)(qb + (size_t)row*1024 + k2*2);
        uint32_t hi, lo; split_pair(v.x, v.y, hi, lo);
        QH[row*PS + k2] = hi; QL[row*PS + k2] = lo;
    }
    // relative-position terms
    for (int w = t; w < 8192; w += 512) {
        if (w < 4096) {
            int row = w >> 5, k = w & 31;
            int ig = (mt*128 + row) >> 5;
            const float* e  = row_emb + (k - ig + 31)*64;
            const float* qv = qb + (size_t)row*1024;
            float s = 0.f;
            #pragma unroll 16
            for (int d = 0; d < 64; d++) s += qv[d]*e[d];
            RR[row*32 + k] = s;
        } else {
            int w2 = w - 4096;
            int row = w2 >> 5, l = w2 & 31;
            int jg = (mt*128 + row) & 31;
            const float* e  = col_emb + (l - jg + 31)*64;
            const float* qv = qb + (size_t)row*1024 + 64;
            float s = 0.f;
            #pragma unroll 16
            for (int d = 0; d < 64; d++) s += qv[d]*e[d];
            RC[row*32 + l] = s;
        }
    }

    const float* kb = g_k + (size_t)b*1024*1024 + h*128;
    const int r0 = rowgrp*16 + gid, r1 = r0 + 8;
    const int rg0 = mt*128 + r0, rg1 = mt*128 + r1;
    float* prow0 = P + ((((size_t)b*32 + (rg0 & 31))*32 + (rg0 >> 5))*8 + h)*1024;
    float* prow1 = P + ((((size_t)b*32 + (rg1 & 31))*32 + (rg1 >> 5))*8 + h)*1024;
    float z0 = 0.f, z1 = 0.f;

    // preload K chunk 0 into registers
    float2 kreg[16];
    #pragma unroll
    for (int i = 0; i < 16; i++) {
        int w = t + i*512;
        int np = w >> 6, k2 = w & 63;
        int src = ((np & 31)*32 + (np >> 5));   // n = np for c=0
        kreg[i] = *(const float2*)(kb + (size_t)src*1024 + k2*2);
    }

    for (int c = 0; c < 8; c++) {
        __syncthreads();   // previous chunk's compute done before K overwrite
        #pragma unroll
        for (int i = 0; i < 16; i++) {
            int w = t + i*512;
            int np = w >> 6, k2 = w & 63;
            uint32_t hi, lo; split_pair(kreg[i].x, kreg[i].y, hi, lo);
            KH[np*PS + k2] = hi; KL[np*PS + k2] = lo;
        }
        __syncthreads();
        if (c < 7) {
            #pragma unroll
            for (int i = 0; i < 16; i++) {
                int w = t + i*512;
                int np = w >> 6, k2 = w & 63;
                int n = (c+1)*128 + np;
                int src = (n & 31)*32 + (n >> 5);
                kreg[i] = *(const float2*)(kb + (size_t)src*1024 + k2*2);
            }
        }

        float acc[8][4];
        #pragma unroll
        for (int n = 0; n < 8; n++)
            #pragma unroll
            for (int u = 0; u < 4; u++) acc[n][u] = 0.f;

        #pragma unroll
        for (int ks = 0; ks < 8; ks++) {
            uint32_t aH[4], aL[4];
            int ca = 8*ks + tig;
            aH[0] = QH[r0*PS + ca];     aH[1] = QH[r1*PS + ca];
            aH[2] = QH[r0*PS + ca + 4]; aH[3] = QH[r1*PS + ca + 4];
            aL[0] = QL[r0*PS + ca];     aL[1] = QL[r1*PS + ca];
            aL[2] = QL[r0*PS + ca + 4]; aL[3] = QL[r1*PS + ca + 4];
            #pragma unroll
            for (int n = 0; n < 8; n++) {
                int nt = colhalf*8 + n;
                uint32_t bH[2], bL[2];
                int nb = (8*nt + gid)*PS + ca;
                bH[0] = KH[nb]; bH[1] = KH[nb + 4];
                bL[0] = KL[nb]; bL[1] = KL[nb + 4];
                mma_bf16(acc[n], aH, bH);
                mma_bf16(acc[n], aH, bL);
                mma_bf16(acc[n], aL, bH);
            }
        }

        // epilogue: +rel, exp, accumulate z, store unnormalized probs
        #pragma unroll
        for (int n = 0; n < 8; n++) {
            int nt = colhalf*8 + n;
            int cn = 8*nt + 2*tig;
            int cg = c*128 + cn;
            int l = cg >> 5;
            int k0 = cg & 31, k1 = k0 + 1;
            float rcr0 = RC[r0*32 + l], rcr1 = RC[r1*32 + l];
            float p00 = __expf(SCALE*(acc[n][0] + RR[r0*32 + k0] + rcr0));
            float p01 = __expf(SCALE*(acc[n][1] + RR[r0*32 + k1] + rcr0));
            float p10 = __expf(SCALE*(acc[n][2] + RR[r1*32 + k0] + rcr1));
            float p11 = __expf(SCALE*(acc[n][3] + RR[r1*32 + k1] + rcr1));
            z0 += p00 + p01;
            z1 += p10 + p11;
            *(float2*)(prow0 + cg) = make_float2(p00, p01);
            *(float2*)(prow1 + cg) = make_float2(p10, p11);
        }
    }

    // z: reduce over tig lanes, combine column halves via smem
    z0 += __shfl_xor_sync(0xffffffffu, z0, 1);
    z0 += __shfl_xor_sync(0xffffffffu, z0, 2);
    z1 += __shfl_xor_sync(0xffffffffu, z1, 1);
    z1 += __shfl_xor_sync(0xffffffffu, z1, 2);
    if (tig == 0) {
        ZP[colhalf*128 + r0] = z0;
        ZP[colhalf*128 + r1] = z1;
    }
    __syncthreads();
    if (t < 128) {
        float z = ZP[t] + ZP[128 + t];
        g_rz[((size_t)b*8 + h)*1024 + mt*128 + t] = 1.0f / z;
    }
}

// ---------------------------------------- normalize probs in place (P *= rz)
__global__ void __launch_bounds__(256) norm_kernel(float* __restrict__ P) {
    size_t i4 = (size_t)blockIdx.x*256 + threadIdx.x;   // 16,777,216 float4s
    size_t e = i4 * 4;
    int hh = (int)((e >> 10) & 7);
    int ii = (int)((e >> 13) & 31);
    int jj = (int)((e >> 18) & 31);
    int bb = (int)(e >> 23);
    float rz = g_rz[(((size_t)bb*8 + hh) << 10) + ii*32 + jj];
    float4 v = ((float4*)P)[i4];
    v.x *= rz; v.y *= rz; v.z *= rz; v.w *= rz;
    ((float4*)P)[i4] = v;
}

// ================================================ mma.sync context GEMM kernel
// CTA = (mt, h, b), 512 threads / 16 warps; persistent acc over 8 seq-chunks.
#define CT_AH   0
#define CT_AL   34816
#define CT_BH   69632
#define CT_BL   104448
#define CT_SMEM 139264

__global__ void __launch_bounds__(512, 1)
ctx_kernel(const float* __restrict__ P)
{
    extern __shared__ char smc[];
    uint32_t* AH = (uint32_t*)(smc + CT_AH);
    uint32_t* AL = (uint32_t*)(smc + CT_AL);
    uint32_t* BH = (uint32_t*)(smc + CT_BH);
    uint32_t* BL = (uint32_t*)(smc + CT_BL);

    const int t = threadIdx.x;
    const int wid = t >> 5, lane = t & 31;
    const int gid = lane >> 2, tig = lane & 3;
    const int rowgrp = wid & 7, colhalf = wid >> 3;
    const int mt = blockIdx.x, h = blockIdx.y, b = blockIdx.z;

    const uint32_t* xh = (const uint32_t*)g_xth;
    const uint32_t* xl = (const uint32_t*)g_xtl;

    float acc[8][4];
    #pragma unroll
    for (int n = 0; n < 8; n++)
        #pragma unroll
        for (int u = 0; u < 4; u++) acc[n][u] = 0.f;

    const int r0 = rowgrp*16 + gid, r1 = r0 + 8;

    // preload A chunk 0 (normalized probs)
    float2 areg[16];
    #pragma unroll
    for (int i = 0; i < 16; i++) {
        int w = t + i*512;
        int m = w >> 6, k2 = w & 63;
        int r2 = mt*128 + m;
        const float* arow = P + ((((size_t)b*32 + (r2 >> 5))*32 + (r2 & 31))*8 + h)*1024;
        areg[i] = *(const float2*)(arow + k2*2);
    }

    for (int c = 0; c < 8; c++) {
        __syncthreads();
        #pragma unroll
        for (int i = 0; i < 16; i++) {
            int w = t + i*512;
            int m = w >> 6, k2 = w & 63;
            uint32_t hi, lo; split_pair(areg[i].x, areg[i].y, hi, lo);
            AH[m*PS + k2] = hi; AL[m*PS + k2] = lo;
        }
        // B = x^T (bf16 hi/lo, [b][d][n]) — L2-hot
        #pragma unroll
        for (int i = 0; i < 16; i++) {
            int w = t + i*512;
            int dp = w >> 6, k2 = w & 63;
            size_t idx = ((size_t)b*128 + dp)*512 + c*64 + k2;   // uint32 units
            BH[dp*PS + k2] = xh[idx];
            BL[dp*PS + k2] = xl[idx];
        }
        __syncthreads();
        if (c < 7) {
            #pragma unroll
            for (int i = 0; i < 16; i++) {
                int w = t + i*512;
                int m = w >> 6, k2 = w & 63;
                int r2 = mt*128 + m;
                const float* arow = P + ((((size_t)b*32 + (r2 >> 5))*32 + (r2 & 31))*8 + h)*1024
                                      + (c+1)*128;
                areg[i] = *(const float2*)(arow + k2*2);
            }
        }

        #pragma unroll
        for (int ks = 0; ks < 8; ks++) {
            uint32_t aH[4], aL[4];
            int ca = 8*ks + tig;
            aH[0] = AH[r0*PS + ca];     aH[1] = AH[r1*PS + ca];
            aH[2] = AH[r0*PS + ca + 4]; aH[3] = AH[r1*PS + ca + 4];
            aL[0] = AL[r0*PS + ca];     aL[1] = AL[r1*PS + ca];
            aL[2] = AL[r0*PS + ca + 4]; aL[3] = AL[r1*PS + ca + 4];
            #pragma unroll
            for (int n = 0; n < 8; n++) {
                int nt = colhalf*8 + n;
                uint32_t bH[2], bL[2];
                int nb = (8*nt + gid)*PS + ca;
                bH[0] = BH[nb]; bH[1] = BH[nb + 4];
                bL[0] = BL[nb]; bL[1] = BL[nb + 4];
                mma_bf16(acc[n], aH, bH);
                mma_bf16(acc[n], aH, bL);
                mma_bf16(acc[n], aL, bH);
            }
        }
    }

    // epilogue: write g_ctx rows
    {
        int r2a = mt*128 + r0, r2b = mt*128 + r1;
        float* oa = g_ctx + ((size_t)b*1024 + r2a)*1024 + h*128;
        float* ob = g_ctx + ((size_t)b*1024 + r2b)*1024 + h*128;
        #pragma unroll
        for (int n = 0; n < 8; n++) {
            int cn = 8*(colhalf*8 + n) + 2*tig;
            *(float2*)(oa + cn) = make_float2(acc[n][0], acc[n][1]);
            *(float2*)(ob + cn) = make_float2(acc[n][2], acc[n][3]);
        }
    }
}

// ================================================ tensorized output projection
// CTA = 64-row tile (grid 128). out = ctx(64x1024) x Wv^T(128x1024) + bv + x.
#define OU_AH   0
#define OU_AL   17408
#define OU_BH   34816
#define OU_BL   69632
#define OU_SMEM 104448

__global__ void __launch_bounds__(512, 1)
out_mma_kernel(const float* __restrict__ Wv, const float* __restrict__ bv,
               float* __restrict__ out)
{
    extern __shared__ char smc[];
    uint32_t* AH = (uint32_t*)(smc + OU_AH);
    uint32_t* AL = (uint32_t*)(smc + OU_AL);
    uint32_t* BH = (uint32_t*)(smc + OU_BH);
    uint32_t* BL = (uint32_t*)(smc + OU_BL);

    const int t = threadIdx.x;
    const int wid = t >> 5, lane = t & 31;
    const int gid = lane >> 2, tig = lane & 3;
    const int rowgrp = wid & 3, colq = wid >> 2;    // 4 row groups x 4 col quarters
    const int bx = blockIdx.x;

    float acc[4][4];
    #pragma unroll
    for (int n = 0; n < 4; n++)
        #pragma unroll
        for (int u = 0; u < 4; u++) acc[n][u] = 0.f;

    const int r0 = rowgrp*16 + gid, r1 = r0 + 8;

    for (int c = 0; c < 8; c++) {
        __syncthreads();
        // A: 64 rows x 128 K-cols of g_ctx
        #pragma unroll
        for (int i = 0; i < 8; i++) {
            int w = t + i*512;
            int row = w >> 6, k2 = w & 63;
            float2 v = *(const float2*)(g_ctx + (size_t)(bx*64 + row)*1024 + c*128 + k2*2);
            uint32_t hi, lo; split_pair(v.x, v.y, hi, lo);
            AH[row*PS + k2] = hi; AL[row*PS + k2] = lo;
        }
        // B: Wv rows (128 o) x 128 K-cols
        #pragma unroll
        for (int i = 0; i < 16; i++) {
            int w = t + i*512;
            int o = w >> 6, k2 = w & 63;
            float2 v = *(const float2*)(Wv + (size_t)o*1024 + c*128 + k2*2);
            uint32_t hi, lo; split_pair(v.x, v.y, hi, lo);
            BH[o*PS + k2] = hi; BL[o*PS + k2] = lo;
        }
        __syncthreads();

        #pragma unroll
        for (int ks = 0; ks < 8; ks++) {
            uint32_t aH[4], aL[4];
            int ca = 8*ks + tig;
            aH[0] = AH[r0*PS + ca];     aH[1] = AH[r1*PS + ca];
            aH[2] = AH[r0*PS + ca + 4]; aH[3] = AH[r1*PS + ca + 4];
            aL[0] = AL[r0*PS + ca];     aL[1] = AL[r1*PS + ca];
            aL[2] = AL[r0*PS + ca + 4]; aL[3] = AL[r1*PS + ca + 4];
            #pragma unroll
            for (int n = 0; n < 4; n++) {
                int nt = colq*4 + n;
                uint32_t bH[2], bL[2];
                int nb = (8*nt + gid)*PS + ca;
                bH[0] = BH[nb]; bH[1] = BH[nb + 4];
                bL[0] = BL[nb]; bL[1] = BL[nb + 4];
                mma_bf16(acc[n], aH, bH);
                mma_bf16(acc[n], aH, bL);
                mma_bf16(acc[n], aL, bH);
            }
        }
    }

    // epilogue: + bias + residual
    {
        size_t ra = (size_t)(bx*64 + r0), rb = (size_t)(bx*64 + r1);
        #pragma unroll
        for (int n = 0; n < 4; n++) {
            int o = 8*(colq*4 + n) + 2*tig;
            float b0 = bv[o], b1 = bv[o+1];
            float2 xa = *(const float2*)(g_x + ra*128 + o);
            float2 xb = *(const float2*)(g_x + rb*128 + o);
            *(float2*)(out + ra*128 + o) = make_float2(acc[n][0] + b0 + xa.x,
                                                       acc[n][1] + b1 + xa.y);
            *(float2*)(out + rb*128 + o) = make_float2(acc[n][2] + b0 + xb.x,
                                                       acc[n][3] + b1 + xb.y);
        }
    }
}

// ---------------------------------------------------------------- launcher
extern "C" void kernel_launch(void* const* d_in, const int* in_sizes, int n_in,
                              void* d_out, int out_size) {
    const float* hs      = (const float*)d_in[0];
    const float* row_emb = (const float*)d_in[1];
    const float* col_emb = (const float*)d_in[2];
    const float* Wq      = (const float*)d_in[3];
    const float* Wk      = (const float*)d_in[4];
    const float* Wv      = (const float*)d_in[5];
    const float* bv      = (const float*)d_in[6];
    const float* ln_g    = (const float*)d_in[7];
    const float* ln_b    = (const float*)d_in[8];
    float* out = (float*)d_out;

    int write_probs = (out_size >= 1048576 + 67108864) ? 1 : 0;
    float* P;
    if (write_probs) {
        P = out + 1048576;
    } else {
        cudaGetSymbolAddress((void**)&P, g_pscratch);
    }

    cudaFuncSetAttribute(qk_mma_kernel,  cudaFuncAttributeMaxDynamicSharedMemorySize, QK_SMEM);
    cudaFuncSetAttribute(scores_kernel,  cudaFuncAttributeMaxDynamicSharedMemorySize, SC_SMEM);
    cudaFuncSetAttribute(ctx_kernel,     cudaFuncAttributeMaxDynamicSharedMemorySize, CT_SMEM);
    cudaFuncSetAttribute(out_mma_kernel, cudaFuncAttributeMaxDynamicSharedMemorySize, OU_SMEM);

    ln_kernel<<<8192, 128>>>(hs, ln_g, ln_b);

    dim3 gxt(32, 4, BSZ);
    xt_kernel<<<gxt, 256>>>();

    dim3 gqk(64, 16);
    qk_mma_kernel<<<gqk, 512, QK_SMEM>>>(Wq, Wk);

    dim3 gsc(8, NHEADS, BSZ);
    scores_kernel<<<gsc, 512, SC_SMEM>>>(row_emb, col_emb, P);

    norm_kernel<<<65536, 256>>>(P);

    dim3 gct(8, NHEADS, BSZ);
    ctx_kernel<<<gct, 512, CT_SMEM>>>(P);

    out_mma_kernel<<<128, 512, OU_SMEM>>>(Wv, bv, out);
}

// round 12
// speedup vs baseline: 2.4723x; 1.0139x over previous
#include <cuda_runtime.h>
#include <cuda_bf16.h>
#include <math.h>
#include <stdint.h>

// Problem constants
#define BSZ 8
#define HW 32
#define DMODEL 128
#define NHEADS 8
#define SCALE 0.08838834764831845f   // 1/sqrt(128)
#define PS 68                         // smem row stride in uint32 (conflict-free: bank=4*gid+tig)

// ---------------------------------------------------------------- scratch
__device__ float g_x  [BSZ*HW*HW*DMODEL];            // LN output  (4 MB)
__device__ float g_q  [BSZ*HW*HW*NHEADS*DMODEL];     // 32 MB
__device__ float g_k  [BSZ*HW*HW*NHEADS*DMODEL];     // 32 MB
__device__ float g_ctx[BSZ*HW*HW*NHEADS*DMODEL];     // 32 MB
__device__ __nv_bfloat16 g_xth[BSZ*DMODEL*1024];     // x^T hi  (2 MB)  [b][d][n]
__device__ __nv_bfloat16 g_xtl[BSZ*DMODEL*1024];     // x^T lo  (2 MB)
__device__ float g_pscratch[67108864];               // fallback probs buffer

// fp32 pair -> bf16x2 (hi) + bf16x2 (residual lo)
__device__ __forceinline__ void split_pair(float x, float y, uint32_t& hi, uint32_t& lo) {
    __nv_bfloat16 hx = __float2bfloat16(x), hy = __float2bfloat16(y);
    float rx = x - __bfloat162float(hx), ry = y - __bfloat162float(hy);
    __nv_bfloat162 H; H.x = hx; H.y = hy;
    __nv_bfloat162 L; L.x = __float2bfloat16(rx); L.y = __float2bfloat16(ry);
    hi = *reinterpret_cast<uint32_t*>(&H);
    lo = *reinterpret_cast<uint32_t*>(&L);
}

// warp-level bf16 MMA, m16n8k16, fp32 accumulate (base PTX; works on sm_100)
__device__ __forceinline__ void mma_bf16(float* d, const uint32_t* a, const uint32_t* b) {
    asm volatile(
        "mma.sync.aligned.m16n8k16.row.col.f32.bf16.bf16.f32 "
        "{%0,%1,%2,%3}, {%4,%5,%6,%7}, {%8,%9}, {%0,%1,%2,%3};"
        : "+f"(d[0]), "+f"(d[1]), "+f"(d[2]), "+f"(d[3])
        : "r"(a[0]), "r"(a[1]), "r"(a[2]), "r"(a[3]), "r"(b[0]), "r"(b[1]));
}

// ---------------------------------------------------------------- LayerNorm
__global__ void ln_kernel(const float* __restrict__ hs,
                          const float* __restrict__ gam,
                          const float* __restrict__ bet) {
    int row = blockIdx.x;          // 8192 rows
    int c   = threadIdx.x;         // 128
    float v = hs[row*128 + c];
    float s = v, s2 = v*v;
    #pragma unroll
    for (int o = 16; o >= 1; o >>= 1) {
        s  += __shfl_xor_sync(0xffffffffu, s,  o);
        s2 += __shfl_xor_sync(0xffffffffu, s2, o);
    }
    __shared__ float ws[4], ws2[4];
    int w = c >> 5;
    if ((c & 31) == 0) { ws[w] = s; ws2[w] = s2; }
    __syncthreads();
    s  = ws[0] + ws[1] + ws[2] + ws[3];
    s2 = ws2[0] + ws2[1] + ws2[2] + ws2[3];
    float mu  = s  * (1.0f/128.0f);
    float var = s2 * (1.0f/128.0f) - mu*mu;
    float r   = rsqrtf(var + 1e-5f);
    g_x[row*128 + c] = (v - mu) * r * gam[c] + bet[c];
}

// -------------------------------------------- x transpose -> bf16 hi/lo [b][d][n]
__global__ void __launch_bounds__(256) xt_kernel() {
    __shared__ float sm[32][33];
    int nt = blockIdx.x, dt = blockIdx.y, b = blockIdx.z;
    int t = threadIdx.x;
    #pragma unroll
    for (int it = 0; it < 4; it++) {
        int tn = (t >> 5) + it*8, td = t & 31;
        sm[tn][td] = g_x[((size_t)b*1024 + nt*32 + tn)*128 + dt*32 + td];
    }
    __syncthreads();
    #pragma unroll
    for (int it = 0; it < 2; it++) {
        int w = t + it*256;
        int td = w >> 4, np = w & 15;
        uint32_t hi, lo;
        split_pair(sm[2*np][td], sm[2*np+1][td], hi, lo);
        size_t off = ((size_t)b*128 + dt*32 + td)*1024 + nt*32 + 2*np;
        *reinterpret_cast<uint32_t*>(&g_xth[off]) = hi;
        *reinterpret_cast<uint32_t*>(&g_xtl[off]) = lo;
    }
}

// ================================================ tensorized Q,K projection
#define QK_AH   0
#define QK_AL   34816
#define QK_BH   69632
#define QK_BL   104448
#define QK_SMEM 139264

__global__ void __launch_bounds__(512, 1)
qk_mma_kernel(const float* __restrict__ Wq, const float* __restrict__ Wk) {
    extern __shared__ char smc[];
    uint32_t* AH = (uint32_t*)(smc + QK_AH);
    uint32_t* AL = (uint32_t*)(smc + QK_AL);
    uint32_t* BH = (uint32_t*)(smc + QK_BH);
    uint32_t* BL = (uint32_t*)(smc + QK_BL);
    const int t = threadIdx.x;
    const int wid = t >> 5, lane = t & 31;
    const int gid = lane >> 2, tig = lane & 3;
    const int rowgrp = wid & 7, colhalf = wid >> 3;
    const int bx = blockIdx.x, by = blockIdx.y;

    #pragma unroll
    for (int i = 0; i < 16; i++) {
        int w = t + i*512;
        int row = w >> 6, k2 = w & 63;
        float2 va = *(const float2*)(g_x + (size_t)(bx*128 + row)*128 + k2*2);
        uint32_t hi, lo; split_pair(va.x, va.y, hi, lo);
        AH[row*PS + k2] = hi; AL[row*PS + k2] = lo;
        int o = by*128 + row;
        const float* wr = (o < 1024) ? (Wq + (size_t)o*128) : (Wk + (size_t)(o-1024)*128);
        float2 vb = *(const float2*)(wr + k2*2);
        split_pair(vb.x, vb.y, hi, lo);
        BH[row*PS + k2] = hi; BL[row*PS + k2] = lo;
    }
    __syncthreads();

    const int r0 = rowgrp*16 + gid, r1 = r0 + 8;
    float acc[8][4];
    #pragma unroll
    for (int n = 0; n < 8; n++)
        #pragma unroll
        for (int u = 0; u < 4; u++) acc[n][u] = 0.f;

    #pragma unroll
    for (int ks = 0; ks < 8; ks++) {
        uint32_t aH[4], aL[4];
        int ca = 8*ks + tig;
        aH[0] = AH[r0*PS + ca];     aH[1] = AH[r1*PS + ca];
        aH[2] = AH[r0*PS + ca + 4]; aH[3] = AH[r1*PS + ca + 4];
        aL[0] = AL[r0*PS + ca];     aL[1] = AL[r1*PS + ca];
        aL[2] = AL[r0*PS + ca + 4]; aL[3] = AL[r1*PS + ca + 4];
        #pragma unroll
        for (int n = 0; n < 8; n++) {
            int nt = colhalf*8 + n;
            uint32_t bH[2], bL[2];
            int nb = (8*nt + gid)*PS + ca;
            bH[0] = BH[nb]; bH[1] = BH[nb + 4];
            bL[0] = BL[nb]; bL[1] = BL[nb + 4];
            mma_bf16(acc[n], aH, bH);
            mma_bf16(acc[n], aH, bL);
            mma_bf16(acc[n], aL, bH);
        }
    }

    #pragma unroll
    for (int n = 0; n < 8; n++) {
        int nt = colhalf*8 + n;
        int cn = 8*nt + 2*tig;
        int colg = by*128 + cn;
        size_t ra = (size_t)(bx*128 + r0), rb = (size_t)(bx*128 + r1);
        if (by < 8) {
            *(float2*)(g_q + ra*1024 + colg)          = make_float2(acc[n][0], acc[n][1]);
            *(float2*)(g_q + rb*1024 + colg)          = make_float2(acc[n][2], acc[n][3]);
        } else {
            *(float2*)(g_k + ra*1024 + (colg - 1024)) = make_float2(acc[n][0], acc[n][1]);
            *(float2*)(g_k + rb*1024 + (colg - 1024)) = make_float2(acc[n][2], acc[n][3]);
        }
    }
}

// ================================================ FUSED attention kernel
// CTA = (mt, h, b), 512 threads / 16 warps.
// Per 128-col chunk: S = Q·K^T (3 bf16 chains) -> exp in regs -> exp tile
// into K buffers (bf16 hi/lo) -> ctx += exp·X^T chunk (3 chains).
// Unnormalized exp streamed to P; tail normalizes P in place (L2-hot) and
// scales ctx rows by 1/z.
#define FS_QH   0
#define FS_QL   34816
#define FS_KH   69632       // reused as A (exp tile) for ctx MMA
#define FS_KL   104448
#define FS_XH   139264
#define FS_XL   174080
#define FS_RR   208896      // bf16 128x32
#define FS_RC   217088      // bf16 128x32
#define FS_ZP   225280      // fp32 256
#define FS_RZ   226304      // fp32 128
#define FS_SMEM 226816

__global__ void __launch_bounds__(512, 1)
attn_fused(const float* __restrict__ row_emb, const float* __restrict__ col_emb,
           float* __restrict__ P)
{
    extern __shared__ char smc[];
    uint32_t* QH = (uint32_t*)(smc + FS_QH);
    uint32_t* QL = (uint32_t*)(smc + FS_QL);
    uint32_t* KH = (uint32_t*)(smc + FS_KH);
    uint32_t* KL = (uint32_t*)(smc + FS_KL);
    uint32_t* XH = (uint32_t*)(smc + FS_XH);
    uint32_t* XL = (uint32_t*)(smc + FS_XL);
    __nv_bfloat16* RR = (__nv_bfloat16*)(smc + FS_RR);
    __nv_bfloat16* RC = (__nv_bfloat16*)(smc + FS_RC);
    float* ZP = (float*)(smc + FS_ZP);
    float* RZ = (float*)(smc + FS_RZ);

    const int t = threadIdx.x;
    const int wid = t >> 5, lane = t & 31;
    const int gid = lane >> 2, tig = lane & 3;
    const int rowgrp = wid & 7, colhalf = wid >> 3;
    const int mt = blockIdx.x, h = blockIdx.y, b = blockIdx.z;

    const float* qb = g_q + ((size_t)b*1024 + mt*128)*1024 + h*128;

    // Q tile -> smem hi/lo
    #pragma unroll
    for (int i = 0; i < 16; i++) {
        int w = t + i*512;
        int row = w >> 6, k2 = w & 63;
        float2 v = *(const float2*)(qb + (size_t)row*1024 + k2*2);
        uint32_t hi, lo; split_pair(v.x, v.y, hi, lo);
        QH[row*PS + k2] = hi; QL[row*PS + k2] = lo;
    }
    // relative-position terms (fp32 math, bf16 storage)
    for (int w = t; w < 8192; w += 512) {
        if (w < 4096) {
            int row = w >> 5, k = w & 31;
            int ig = (mt*128 + row) >> 5;
            const float* e  = row_emb + (k - ig + 31)*64;
            const float* qv = qb + (size_t)row*1024;
            float s = 0.f;
            #pragma unroll 16
            for (int d = 0; d < 64; d++) s += qv[d]*e[d];
            RR[row*32 + k] = __float2bfloat16(s);
        } else {
            int w2 = w - 4096;
            int row = w2 >> 5, l = w2 & 31;
            int jg = (mt*128 + row) & 31;
            const float* e  = col_emb + (l - jg + 31)*64;
            const float* qv = qb + (size_t)row*1024 + 64;
            float s = 0.f;
            #pragma unroll 16
            for (int d = 0; d < 64; d++) s += qv[d]*e[d];
            RC[row*32 + l] = __float2bfloat16(s);
        }
    }

    const float*    kb = g_k + (size_t)b*1024*1024 + h*128;
    const uint32_t* xh = (const uint32_t*)g_xth;
    const uint32_t* xl = (const uint32_t*)g_xtl;

    const int r0 = rowgrp*16 + gid, r1 = r0 + 8;
    const int rg0 = mt*128 + r0, rg1 = mt*128 + r1;
    float* prow0 = P + ((((size_t)b*32 + (rg0 & 31))*32 + (rg0 >> 5))*8 + h)*1024;
    float* prow1 = P + ((((size_t)b*32 + (rg1 & 31))*32 + (rg1 >> 5))*8 + h)*1024;
    float z0 = 0.f, z1 = 0.f;

    float cacc[8][4];
    #pragma unroll
    for (int n = 0; n < 8; n++)
        #pragma unroll
        for (int u = 0; u < 4; u++) cacc[n][u] = 0.f;

    for (int c = 0; c < 8; c++) {
        __syncthreads();   // prev ctx MMA done reading A/X (and Q/rel stores at c=0)
        // K chunk -> KH/KL
        #pragma unroll
        for (int i = 0; i < 16; i++) {
            int w = t + i*512;
            int np = w >> 6, k2 = w & 63;
            int n = c*128 + np;
            int src = (n & 31)*32 + (n >> 5);
            float2 v = *(const float2*)(kb + (size_t)src*1024 + k2*2);
            uint32_t hi, lo; split_pair(v.x, v.y, hi, lo);
            KH[np*PS + k2] = hi; KL[np*PS + k2] = lo;
        }
        // X^T chunk -> XH/XL
        #pragma unroll
        for (int i = 0; i < 16; i++) {
            int w = t + i*512;
            int dp = w >> 6, k2 = w & 63;
            size_t idx = ((size_t)b*128 + dp)*512 + c*64 + k2;   // uint32 units
            XH[dp*PS + k2] = xh[idx];
            XL[dp*PS + k2] = xl[idx];
        }
        __syncthreads();

        // ---- scores MMA: S = Q · K^T
        float sacc[8][4];
        #pragma unroll
        for (int n = 0; n < 8; n++)
            #pragma unroll
            for (int u = 0; u < 4; u++) sacc[n][u] = 0.f;
        #pragma unroll
        for (int ks = 0; ks < 8; ks++) {
            uint32_t aH[4], aL[4];
            int ca = 8*ks + tig;
            aH[0] = QH[r0*PS + ca];     aH[1] = QH[r1*PS + ca];
            aH[2] = QH[r0*PS + ca + 4]; aH[3] = QH[r1*PS + ca + 4];
            aL[0] = QL[r0*PS + ca];     aL[1] = QL[r1*PS + ca];
            aL[2] = QL[r0*PS + ca + 4]; aL[3] = QL[r1*PS + ca + 4];
            #pragma unroll
            for (int n = 0; n < 8; n++) {
                int nt = colhalf*8 + n;
                uint32_t bH[2], bL[2];
                int nb = (8*nt + gid)*PS + ca;
                bH[0] = KH[nb]; bH[1] = KH[nb + 4];
                bL[0] = KL[nb]; bL[1] = KL[nb + 4];
                mma_bf16(sacc[n], aH, bH);
                mma_bf16(sacc[n], aH, bL);
                mma_bf16(sacc[n], aL, bH);
            }
        }

        // ---- epilogue: exp, z, stream unnormalized P, keep bf16 hi/lo
        uint32_t eh0[8], el0[8], eh1[8], el1[8];
        #pragma unroll
        for (int n = 0; n < 8; n++) {
            int nt = colhalf*8 + n;
            int cn = 8*nt + 2*tig;
            int cg = c*128 + cn;
            int l = cg >> 5;
            int k0 = cg & 31, k1 = k0 + 1;
            float rcr0 = __bfloat162float(RC[r0*32 + l]);
            float rcr1 = __bfloat162float(RC[r1*32 + l]);
            float p00 = __expf(SCALE*(sacc[n][0] + __bfloat162float(RR[r0*32 + k0]) + rcr0));
            float p01 = __expf(SCALE*(sacc[n][1] + __bfloat162float(RR[r0*32 + k1]) + rcr0));
            float p10 = __expf(SCALE*(sacc[n][2] + __bfloat162float(RR[r1*32 + k0]) + rcr1));
            float p11 = __expf(SCALE*(sacc[n][3] + __bfloat162float(RR[r1*32 + k1]) + rcr1));
            z0 += p00 + p01;
            z1 += p10 + p11;
            *(float2*)(prow0 + cg) = make_float2(p00, p01);
            *(float2*)(prow1 + cg) = make_float2(p10, p11);
            split_pair(p00, p01, eh0[n], el0[n]);
            split_pair(p10, p11, eh1[n], el1[n]);
        }
        __syncthreads();   // all warps done with K reads for scores
        // exp tile -> KH/KL (A operand for ctx MMA)
        #pragma unroll
        for (int n = 0; n < 8; n++) {
            int nt = colhalf*8 + n;
            int k2 = 4*nt + tig;      // pair index of cols (8nt+2tig, +1)
            KH[r0*PS + k2] = eh0[n];  KL[r0*PS + k2] = el0[n];
            KH[r1*PS + k2] = eh1[n];  KL[r1*PS + k2] = el1[n];
        }
        __syncthreads();

        // ---- ctx MMA: cacc += exp · X^T
        #pragma unroll
        for (int ks = 0; ks < 8; ks++) {
            uint32_t aH[4], aL[4];
            int ca = 8*ks + tig;
            aH[0] = KH[r0*PS + ca];     aH[1] = KH[r1*PS + ca];
            aH[2] = KH[r0*PS + ca + 4]; aH[3] = KH[r1*PS + ca + 4];
            aL[0] = KL[r0*PS + ca];     aL[1] = KL[r1*PS + ca];
            aL[2] = KL[r0*PS + ca + 4]; aL[3] = KL[r1*PS + ca + 4];
            #pragma unroll
            for (int n = 0; n < 8; n++) {
                int nt = colhalf*8 + n;
                uint32_t bH[2], bL[2];
                int nb = (8*nt + gid)*PS + ca;
                bH[0] = XH[nb]; bH[1] = XH[nb + 4];
                bL[0] = XL[nb]; bL[1] = XL[nb + 4];
                mma_bf16(cacc[n], aH, bH);
                mma_bf16(cacc[n], aH, bL);
                mma_bf16(cacc[n], aL, bH);
            }
        }
    }

    // ---- z reduction -> RZ
    z0 += __shfl_xor_sync(0xffffffffu, z0, 1);
    z0 += __shfl_xor_sync(0xffffffffu, z0, 2);
    z1 += __shfl_xor_sync(0xffffffffu, z1, 1);
    z1 += __shfl_xor_sync(0xffffffffu, z1, 2);
    if (tig == 0) {
        ZP[colhalf*128 + r0] = z0;
        ZP[colhalf*128 + r1] = z1;
    }
    __syncthreads();
    if (t < 128) RZ[t] = 1.0f / (ZP[t] + ZP[128 + t]);
    __syncthreads();

    // ---- ctx epilogue: scale by 1/z, write g_ctx (row r2 = j*32 + i)
    {
        float s0 = RZ[r0], s1 = RZ[r1];
        int r2a = (rg0 & 31)*32 + (rg0 >> 5);
        int r2b = (rg1 & 31)*32 + (rg1 >> 5);
        float* oa = g_ctx + ((size_t)b*1024 + r2a)*1024 + h*128;
        float* ob = g_ctx + ((size_t)b*1024 + r2b)*1024 + h*128;
        #pragma unroll
        for (int n = 0; n < 8; n++) {
            int cn = 8*(colhalf*8 + n) + 2*tig;
            *(float2*)(oa + cn) = make_float2(cacc[n][0]*s0, cacc[n][1]*s0);
            *(float2*)(ob + cn) = make_float2(cacc[n][2]*s1, cacc[n][3]*s1);
        }
    }

    // ---- tail: normalize this CTA's P rows in place (L2-hot)
    #pragma unroll
    for (int it = 0; it < 64; it++) {
        int w = t + it*512;                  // 32768 float4s
        int row = w >> 8, c4 = w & 255;
        int rg = mt*128 + row;
        float rz = RZ[row];
        float4* addr = (float4*)(P + ((((size_t)b*32 + (rg & 31))*32 + (rg >> 5))*8 + h)*1024) + c4;
        float4 v = *addr;
        v.x *= rz; v.y *= rz; v.z *= rz; v.w *= rz;
        *addr = v;
    }
}

// ================================================ tensorized output projection
#define OU_AH   0
#define OU_AL   17408
#define OU_BH   34816
#define OU_BL   69632
#define OU_SMEM 104448

__global__ void __launch_bounds__(512, 1)
out_mma_kernel(const float* __restrict__ Wv, const float* __restrict__ bv,
               float* __restrict__ out)
{
    extern __shared__ char smc[];
    uint32_t* AH = (uint32_t*)(smc + OU_AH);
    uint32_t* AL = (uint32_t*)(smc + OU_AL);
    uint32_t* BH = (uint32_t*)(smc + OU_BH);
    uint32_t* BL = (uint32_t*)(smc + OU_BL);

    const int t = threadIdx.x;
    const int wid = t >> 5, lane = t & 31;
    const int gid = lane >> 2, tig = lane & 3;
    const int rowgrp = wid & 3, colq = wid >> 2;
    const int bx = blockIdx.x;

    float acc[4][4];
    #pragma unroll
    for (int n = 0; n < 4; n++)
        #pragma unroll
        for (int u = 0; u < 4; u++) acc[n][u] = 0.f;

    const int r0 = rowgrp*16 + gid, r1 = r0 + 8;

    for (int c = 0; c < 8; c++) {
        __syncthreads();
        #pragma unroll
        for (int i = 0; i < 8; i++) {
            int w = t + i*512;
            int row = w >> 6, k2 = w & 63;
            float2 v = *(const float2*)(g_ctx + (size_t)(bx*64 + row)*1024 + c*128 + k2*2);
            uint32_t hi, lo; split_pair(v.x, v.y, hi, lo);
            AH[row*PS + k2] = hi; AL[row*PS + k2] = lo;
        }
        #pragma unroll
        for (int i = 0; i < 16; i++) {
            int w = t + i*512;
            int o = w >> 6, k2 = w & 63;
            float2 v = *(const float2*)(Wv + (size_t)o*1024 + c*128 + k2*2);
            uint32_t hi, lo; split_pair(v.x, v.y, hi, lo);
            BH[o*PS + k2] = hi; BL[o*PS + k2] = lo;
        }
        __syncthreads();

        #pragma unroll
        for (int ks = 0; ks < 8; ks++) {
            uint32_t aH[4], aL[4];
            int ca = 8*ks + tig;
            aH[0] = AH[r0*PS + ca];     aH[1] = AH[r1*PS + ca];
            aH[2] = AH[r0*PS + ca + 4]; aH[3] = AH[r1*PS + ca + 4];
            aL[0] = AL[r0*PS + ca];     aL[1] = AL[r1*PS + ca];
            aL[2] = AL[r0*PS + ca + 4]; aL[3] = AL[r1*PS + ca + 4];
            #pragma unroll
            for (int n = 0; n < 4; n++) {
                int nt = colq*4 + n;
                uint32_t bH[2], bL[2];
                int nb = (8*nt + gid)*PS + ca;
                bH[0] = BH[nb]; bH[1] = BH[nb + 4];
                bL[0] = BL[nb]; bL[1] = BL[nb + 4];
                mma_bf16(acc[n], aH, bH);
                mma_bf16(acc[n], aH, bL);
                mma_bf16(acc[n], aL, bH);
            }
        }
    }

    {
        size_t ra = (size_t)(bx*64 + r0), rb = (size_t)(bx*64 + r1);
        #pragma unroll
        for (int n = 0; n < 4; n++) {
            int o = 8*(colq*4 + n) + 2*tig;
            float b0 = bv[o], b1 = bv[o+1];
            float2 xa = *(const float2*)(g_x + ra*128 + o);
            float2 xb = *(const float2*)(g_x + rb*128 + o);
            *(float2*)(out + ra*128 + o) = make_float2(acc[n][0] + b0 + xa.x,
                                                       acc[n][1] + b1 + xa.y);
            *(float2*)(out + rb*128 + o) = make_float2(acc[n][2] + b0 + xb.x,
                                                       acc[n][3] + b1 + xb.y);
        }
    }
}

// ---------------------------------------------------------------- launcher
extern "C" void kernel_launch(void* const* d_in, const int* in_sizes, int n_in,
                              void* d_out, int out_size) {
    const float* hs      = (const float*)d_in[0];
    const float* row_emb = (const float*)d_in[1];
    const float* col_emb = (const float*)d_in[2];
    const float* Wq      = (const float*)d_in[3];
    const float* Wk      = (const float*)d_in[4];
    const float* Wv      = (const float*)d_in[5];
    const float* bv      = (const float*)d_in[6];
    const float* ln_g    = (const float*)d_in[7];
    const float* ln_b    = (const float*)d_in[8];
    float* out = (float*)d_out;

    int write_probs = (out_size >= 1048576 + 67108864) ? 1 : 0;
    float* P;
    if (write_probs) {
        P = out + 1048576;
    } else {
        cudaGetSymbolAddress((void**)&P, g_pscratch);
    }

    cudaFuncSetAttribute(qk_mma_kernel,  cudaFuncAttributeMaxDynamicSharedMemorySize, QK_SMEM);
    cudaFuncSetAttribute(attn_fused,     cudaFuncAttributeMaxDynamicSharedMemorySize, FS_SMEM);
    cudaFuncSetAttribute(out_mma_kernel, cudaFuncAttributeMaxDynamicSharedMemorySize, OU_SMEM);

    ln_kernel<<<8192, 128>>>(hs, ln_g, ln_b);

    dim3 gxt(32, 4, BSZ);
    xt_kernel<<<gxt, 256>>>();

    dim3 gqk(64, 16);
    qk_mma_kernel<<<gqk, 512, QK_SMEM>>>(Wq, Wk);

    dim3 gat(8, NHEADS, BSZ);
    attn_fused<<<gat, 512, FS_SMEM>>>(row_emb, col_emb, P);

    out_mma_kernel<<<128, 512, OU_SMEM>>>(Wv, bv, out);
}